// round 1
// baseline (speedup 1.0000x reference)
#include <cuda_runtime.h>
#include <cuda_bf16.h>
#include <math.h>

// ---------------------------------------------------------------------------
// DecoderLayer: x -> QKV -> causal MHA -> O proj -> add+LN -> FFN -> add+LN
// B=8, S=1024, D=768, H=12, Dh=64, DFF=3072. All fp32.
// ---------------------------------------------------------------------------

#define BATCH   8
#define SEQ     1024
#define DMODEL  768
#define NHEADS  12
#define DHEAD   64
#define DFF     3072
#define MROWS   (BATCH*SEQ)          // 8192

// ------------------------- scratch (device globals) ------------------------
__device__ float g_q   [MROWS*DMODEL];   // [b,h,s,d] layout
__device__ float g_k   [MROWS*DMODEL];
__device__ float g_v   [MROWS*DMODEL];
__device__ float g_ctx [MROWS*DMODEL];   // [b,s, h*64+d]
__device__ float g_attn[MROWS*DMODEL];
__device__ float g_out1[MROWS*DMODEL];
__device__ float g_h1  [MROWS*DFF];
__device__ float g_ffn [MROWS*DMODEL];

// ------------------------------- GEMM ---------------------------------------
// C[M,N] = A[M,K] @ B[K,N] + bias, epilogue variants.
// BM=BN=128, BK=8, 256 threads, 8x8 per-thread tile. M%128==0, N%128==0, K%8==0.
#define EPI_BIAS      0
#define EPI_BIAS_RELU 1
#define EPI_QKV       2   // write to [b,h,s,d] head layout (N must be 768)

template <int EPI>
__global__ void __launch_bounds__(256)
gemm_kernel(const float* __restrict__ A, const float* __restrict__ B,
            const float* __restrict__ bias, float* __restrict__ C,
            int M, int N, int K)
{
    __shared__ float As[8][128];
    __shared__ float Bs[8][128];

    const int t  = threadIdx.x;
    const int tx = t & 15;          // 0..15 -> N
    const int ty = t >> 4;          // 0..15 -> M
    const int bx = blockIdx.x;      // N / 128
    const int by = blockIdx.y;      // M / 128

    const int a_row = t >> 1;         // 0..127
    const int a_k   = (t & 1) * 4;    // 0 or 4
    const int b_k   = t >> 5;         // 0..7
    const int b_col = (t & 31) * 4;   // 0..124

    const float* Ag = A + (size_t)(by * 128 + a_row) * K + a_k;
    const float* Bg = B + (size_t)b_k * N + bx * 128 + b_col;

    float acc[8][8];
#pragma unroll
    for (int i = 0; i < 8; i++)
#pragma unroll
        for (int j = 0; j < 8; j++) acc[i][j] = 0.f;

    for (int k0 = 0; k0 < K; k0 += 8) {
        float4 av = *(const float4*)(Ag + k0);
        float4 bv = *(const float4*)(Bg + (size_t)k0 * N);
        __syncthreads();
        As[a_k + 0][a_row] = av.x;
        As[a_k + 1][a_row] = av.y;
        As[a_k + 2][a_row] = av.z;
        As[a_k + 3][a_row] = av.w;
        *(float4*)(&Bs[b_k][b_col]) = bv;
        __syncthreads();

#pragma unroll
        for (int kk = 0; kk < 8; kk++) {
            float a[8], b[8];
            *(float4*)(a)     = *(const float4*)(&As[kk][ty * 8]);
            *(float4*)(a + 4) = *(const float4*)(&As[kk][ty * 8 + 4]);
            *(float4*)(b)     = *(const float4*)(&Bs[kk][tx * 8]);
            *(float4*)(b + 4) = *(const float4*)(&Bs[kk][tx * 8 + 4]);
#pragma unroll
            for (int i = 0; i < 8; i++)
#pragma unroll
                for (int j = 0; j < 8; j++)
                    acc[i][j] += a[i] * b[j];
        }
    }

    const int row0 = by * 128 + ty * 8;
    const int col0 = bx * 128 + tx * 8;
#pragma unroll
    for (int i = 0; i < 8; i++) {
#pragma unroll
        for (int j = 0; j < 8; j++) {
            float v = acc[i][j] + bias[col0 + j];
            if (EPI == EPI_BIAS_RELU) v = fmaxf(v, 0.f);
            if (EPI == EPI_QKV) {
                int row = row0 + i, col = col0 + j;
                int b_  = row >> 10, s = row & 1023;
                int h   = col >> 6,  d = col & 63;
                C[((size_t)(b_ * NHEADS + h) * SEQ + s) * DHEAD + d] = v;
            } else {
                C[(size_t)(row0 + i) * N + col0 + j] = v;
            }
        }
    }
}

// ---------------------------- attention -------------------------------------
// Flash-style fp32, BQ=BK=64, 256 threads. thread t: r=t>>2 (row), c=t&3.
// Each thread owns score cols j=c+4*jj and out cols d=c+4*dd (jj,dd in 0..15).
// Smem: Qs[64][68], Ks[64][68] (reused for P), Vs[64][64]  -> 51200 B dynamic.
#define QSTR 68
#define KSTR 68
#define VSTR 64
#define ATT_SMEM ((64*QSTR + 64*KSTR + 64*VSTR) * 4)

__global__ void __launch_bounds__(256)
attn_kernel(const float* __restrict__ Q, const float* __restrict__ K,
            const float* __restrict__ V, float* __restrict__ ctx)
{
    extern __shared__ float sm[];
    float* Qs = sm;                // 64*68
    float* Ks = sm + 64 * QSTR;    // 64*68, reused as P
    float* Vs = Ks + 64 * KSTR;    // 64*64

    const int qt = blockIdx.x;     // 0..15
    const int bh = blockIdx.y;     // 0..95
    const int t  = threadIdx.x;
    const int r  = t >> 2;         // 0..63
    const int c  = t & 3;          // 0..3
    const int q0 = qt * 64;
    const float scale = 0.125f;    // 1/sqrt(64)

    const float* Qg = Q + ((size_t)bh * SEQ + q0) * DHEAD;

    // load Q tile
    for (int i = t; i < 64 * 16; i += 256) {
        int row = i >> 4, dp = (i & 15) << 2;
        *(float4*)(&Qs[row * QSTR + dp]) = *(const float4*)(Qg + row * DHEAD + dp);
    }

    float m = -INFINITY, l = 0.f;
    float o[16];
#pragma unroll
    for (int i = 0; i < 16; i++) o[i] = 0.f;

    const int qg = q0 + r;

    for (int kt = 0; kt <= qt; kt++) {
        const float* Kg = K + ((size_t)bh * SEQ + kt * 64) * DHEAD;
        const float* Vg = V + ((size_t)bh * SEQ + kt * 64) * DHEAD;

        __syncthreads();   // prior P/V reads done (also fences Q load, iter 0)
        for (int i = t; i < 64 * 16; i += 256) {
            int row = i >> 4, dp = (i & 15) << 2;
            *(float4*)(&Ks[row * KSTR + dp]) = *(const float4*)(Kg + row * DHEAD + dp);
            *(float4*)(&Vs[row * VSTR + dp]) = *(const float4*)(Vg + row * DHEAD + dp);
        }
        __syncthreads();

        // scores: s[jj] = Q[r,:] . K[c+4*jj,:]
        float s[16];
#pragma unroll
        for (int jj = 0; jj < 16; jj++) s[jj] = 0.f;
        for (int d = 0; d < 64; d++) {
            float qv = Qs[r * QSTR + d];
#pragma unroll
            for (int jj = 0; jj < 16; jj++)
                s[jj] += qv * Ks[(c + 4 * jj) * KSTR + d];
        }
#pragma unroll
        for (int jj = 0; jj < 16; jj++) {
            int jgl = kt * 64 + c + 4 * jj;
            s[jj] = s[jj] * scale + (jgl > qg ? -1e9f : 0.f);
        }

        // row max over the 4 threads (they cover all 64 cols)
        float tm = s[0];
#pragma unroll
        for (int jj = 1; jj < 16; jj++) tm = fmaxf(tm, s[jj]);
        tm = fmaxf(tm, __shfl_xor_sync(0xffffffffu, tm, 1));
        tm = fmaxf(tm, __shfl_xor_sync(0xffffffffu, tm, 2));

        float mnew  = fmaxf(m, tm);
        float alpha = __expf(m - mnew);
        float psum  = 0.f;
#pragma unroll
        for (int jj = 0; jj < 16; jj++) {
            s[jj] = __expf(s[jj] - mnew);
            psum += s[jj];
        }
        psum += __shfl_xor_sync(0xffffffffu, psum, 1);
        psum += __shfl_xor_sync(0xffffffffu, psum, 2);
        l = l * alpha + psum;
        m = mnew;
#pragma unroll
        for (int dd = 0; dd < 16; dd++) o[dd] *= alpha;

        __syncthreads();   // everyone done reading Ks
#pragma unroll
        for (int jj = 0; jj < 16; jj++)
            Ks[r * KSTR + c + 4 * jj] = s[jj];   // P into K's buffer
        __syncthreads();

        // O += P @ V
        for (int j2 = 0; j2 < 64; j2++) {
            float pv = Ks[r * KSTR + j2];
#pragma unroll
            for (int dd = 0; dd < 16; dd++)
                o[dd] += pv * Vs[j2 * VSTR + c + 4 * dd];
        }
    }

    const float inv = 1.f / l;
    const int b_ = bh / NHEADS, h = bh % NHEADS;
    float* out = ctx + ((size_t)(b_ * SEQ + qg)) * DMODEL + h * DHEAD;
#pragma unroll
    for (int dd = 0; dd < 16; dd++)
        out[c + 4 * dd] = o[dd] * inv;
}

// ----------------------- fused residual add + LayerNorm ---------------------
__global__ void __launch_bounds__(256)
add_ln_kernel(const float* __restrict__ a, const float* __restrict__ b,
              const float* __restrict__ g, const float* __restrict__ be,
              float* __restrict__ out)
{
    __shared__ float red[8];
    const int row = blockIdx.x;
    const int t   = threadIdx.x;
    const float* ar = a + (size_t)row * DMODEL;
    const float* br = b + (size_t)row * DMODEL;

    float v0 = ar[t]       + br[t];
    float v1 = ar[t + 256] + br[t + 256];
    float v2 = ar[t + 512] + br[t + 512];

    float sum = v0 + v1 + v2;
#pragma unroll
    for (int off = 16; off; off >>= 1) sum += __shfl_xor_sync(0xffffffffu, sum, off);
    if ((t & 31) == 0) red[t >> 5] = sum;
    __syncthreads();
    float tot = 0.f;
#pragma unroll
    for (int w = 0; w < 8; w++) tot += red[w];
    const float mu = tot * (1.f / DMODEL);
    __syncthreads();

    float d0 = v0 - mu, d1 = v1 - mu, d2 = v2 - mu;
    float vs = d0 * d0 + d1 * d1 + d2 * d2;
#pragma unroll
    for (int off = 16; off; off >>= 1) vs += __shfl_xor_sync(0xffffffffu, vs, off);
    if ((t & 31) == 0) red[t >> 5] = vs;
    __syncthreads();
    tot = 0.f;
#pragma unroll
    for (int w = 0; w < 8; w++) tot += red[w];
    const float rstd = rsqrtf(tot * (1.f / DMODEL) + 1e-6f);

    float* o = out + (size_t)row * DMODEL;
    o[t]       = g[t]       * d0 * rstd + be[t];
    o[t + 256] = g[t + 256] * d1 * rstd + be[t + 256];
    o[t + 512] = g[t + 512] * d2 * rstd + be[t + 512];
}

// --------------------------------- launch ------------------------------------
extern "C" void kernel_launch(void* const* d_in, const int* in_sizes, int n_in,
                              void* d_out, int out_size)
{
    const float* x  = (const float*)d_in[0];
    // d_in[1] = look_ahead_mask (causal, hardcoded in attn_kernel)
    const float* wq = (const float*)d_in[2];
    const float* bq = (const float*)d_in[3];
    const float* wk = (const float*)d_in[4];
    const float* bk = (const float*)d_in[5];
    const float* wv = (const float*)d_in[6];
    const float* bv = (const float*)d_in[7];
    const float* wo = (const float*)d_in[8];
    const float* bo = (const float*)d_in[9];
    const float* w1 = (const float*)d_in[10];
    const float* b1 = (const float*)d_in[11];
    const float* w2 = (const float*)d_in[12];
    const float* b2 = (const float*)d_in[13];
    const float* g1 = (const float*)d_in[14];
    const float* be1= (const float*)d_in[15];
    const float* g2 = (const float*)d_in[16];
    const float* be2= (const float*)d_in[17];
    float* out = (float*)d_out;

    float *q, *k, *v, *ctx, *attn, *out1, *h1, *ffn;
    cudaGetSymbolAddress((void**)&q,    g_q);
    cudaGetSymbolAddress((void**)&k,    g_k);
    cudaGetSymbolAddress((void**)&v,    g_v);
    cudaGetSymbolAddress((void**)&ctx,  g_ctx);
    cudaGetSymbolAddress((void**)&attn, g_attn);
    cudaGetSymbolAddress((void**)&out1, g_out1);
    cudaGetSymbolAddress((void**)&h1,   g_h1);
    cudaGetSymbolAddress((void**)&ffn,  g_ffn);

    cudaFuncSetAttribute(attn_kernel,
                         cudaFuncAttributeMaxDynamicSharedMemorySize, ATT_SMEM);

    dim3 g768 (DMODEL / 128, MROWS / 128);   // (6, 64)
    dim3 g3072(DFF    / 128, MROWS / 128);   // (24, 64)

    gemm_kernel<EPI_QKV><<<g768, 256>>>(x, wq, bq, q, MROWS, DMODEL, DMODEL);
    gemm_kernel<EPI_QKV><<<g768, 256>>>(x, wk, bk, k, MROWS, DMODEL, DMODEL);
    gemm_kernel<EPI_QKV><<<g768, 256>>>(x, wv, bv, v, MROWS, DMODEL, DMODEL);

    attn_kernel<<<dim3(SEQ / 64, BATCH * NHEADS), 256, ATT_SMEM>>>(q, k, v, ctx);

    gemm_kernel<EPI_BIAS><<<g768, 256>>>(ctx, wo, bo, attn, MROWS, DMODEL, DMODEL);
    add_ln_kernel<<<MROWS, 256>>>(x, attn, g1, be1, out1);

    gemm_kernel<EPI_BIAS_RELU><<<g3072, 256>>>(out1, w1, b1, h1, MROWS, DFF, DMODEL);
    gemm_kernel<EPI_BIAS><<<g768, 256>>>(h1, w2, b2, ffn, MROWS, DMODEL, DFF);
    add_ln_kernel<<<MROWS, 256>>>(out1, ffn, g2, be2, out);
}

// round 3
// speedup vs baseline: 1.8814x; 1.8814x over previous
#include <cuda_runtime.h>
#include <cuda_bf16.h>
#include <math.h>
#include <stdint.h>

// ---------------------------------------------------------------------------
// DecoderLayer on GB300 (compute_100 PTX -> no tcgen05; use mma.sync HMMA).
// bf16 3-split GEMMs (Ah*Bh + Ah*Bl + Al*Bh, fp32 accum) + fp32 flash attn.
// B=8, S=1024, D=768, H=12, Dh=64, DFF=3072.
// ---------------------------------------------------------------------------
#define BATCH   8
#define SEQ     1024
#define DMODEL  768
#define NHEADS  12
#define DHEAD   64
#define DFF     3072
#define MROWS   (BATCH*SEQ)          // 8192

typedef __nv_bfloat16 bf16;

// ------------------------- scratch (device globals) -------------------------
__device__ bf16  g_xh [MROWS*DMODEL],  g_xl [MROWS*DMODEL];
__device__ bf16  g_wqh[DMODEL*DMODEL], g_wql[DMODEL*DMODEL];
__device__ bf16  g_wkh[DMODEL*DMODEL], g_wkl[DMODEL*DMODEL];
__device__ bf16  g_wvh[DMODEL*DMODEL], g_wvl[DMODEL*DMODEL];
__device__ bf16  g_woh[DMODEL*DMODEL], g_wol[DMODEL*DMODEL];
__device__ bf16  g_w1h[DFF*DMODEL],    g_w1l[DFF*DMODEL];    // [N=3072, K=768]
__device__ bf16  g_w2h[DMODEL*DFF],    g_w2l[DMODEL*DFF];    // [N=768, K=3072]
__device__ float g_q   [MROWS*DMODEL];   // [b,h,s,d]
__device__ float g_k   [MROWS*DMODEL];
__device__ float g_v   [MROWS*DMODEL];
__device__ bf16  g_ch [MROWS*DMODEL],  g_cl [MROWS*DMODEL];  // ctx hi/lo
__device__ float g_attn[MROWS*DMODEL];
__device__ float g_out1[MROWS*DMODEL];
__device__ bf16  g_o1h[MROWS*DMODEL],  g_o1l[MROWS*DMODEL];
__device__ bf16  g_h1h[MROWS*DFF],     g_h1l[MROWS*DFF];
__device__ float g_ffn [MROWS*DMODEL];

// ------------------------------ PTX helpers ---------------------------------
__device__ __forceinline__ uint32_t smem_u32(const void* p) {
    uint32_t a;
    asm("{ .reg .u64 t; cvta.to.shared.u64 t, %1; cvt.u32.u64 %0, t; }"
        : "=r"(a) : "l"(p));
    return a;
}

#define CP16(dst, src) \
    asm volatile("cp.async.cg.shared.global [%0], [%1], 16;" \
                 :: "r"(dst), "l"(src))
#define CP_COMMIT() asm volatile("cp.async.commit_group;" ::: "memory")
#define CP_WAIT(n)  asm volatile("cp.async.wait_group %0;" :: "n"(n) : "memory")

#define LDM_X4(r, a) \
    asm volatile("ldmatrix.sync.aligned.m8n8.x4.shared.b16 {%0,%1,%2,%3}, [%4];" \
        : "=r"((r)[0]), "=r"((r)[1]), "=r"((r)[2]), "=r"((r)[3]) : "r"(a))

#define MMA16816(d, a, b0, b1) \
    asm volatile("mma.sync.aligned.m16n8k16.row.col.f32.bf16.bf16.f32 " \
        "{%0,%1,%2,%3}, {%4,%5,%6,%7}, {%8,%9}, {%0,%1,%2,%3};" \
        : "+f"((d)[0]), "+f"((d)[1]), "+f"((d)[2]), "+f"((d)[3]) \
        : "r"((a)[0]), "r"((a)[1]), "r"((a)[2]), "r"((a)[3]), "r"(b0), "r"(b1))

// ---------------------- HMMA GEMM: C = A @ B^T + bias -----------------------
// A: [M, K] bf16 (hi/lo) row-major; B: [N, K] bf16 (hi/lo) row-major.
// BM=BN=128, BK=32. 256 threads = 8 warps (2 x 4), warp tile 64x32.
// EPI: 0 = fp32 [M,N]; 1 = fp32 scatter to [b,h,s,d]; 2 = ReLU + bf16 hi/lo.
#define GLDA   40                    // padded row, elements (80 B)
#define GTILE  (128 * GLDA * 2)      // 10240 B per array
#define GSTAGE (4 * GTILE)           // Ah, Al, Bh, Bl
#define GSMEM  (2 * GSTAGE)          // 81920 B

template<int EPI>
__global__ void __launch_bounds__(256, 1)
mma_gemm(const bf16* __restrict__ Ah_, const bf16* __restrict__ Al_,
         const bf16* __restrict__ Bh_, const bf16* __restrict__ Bl_,
         const float* __restrict__ bias,
         float* __restrict__ Cf, bf16* __restrict__ Ch, bf16* __restrict__ Cl,
         int N, int K)
{
    extern __shared__ __align__(128) char smem[];
    const uint32_t sb = smem_u32(smem);
    const int tid  = threadIdx.x;
    const int lane = tid & 31;
    const int wm   = (tid >> 5) & 1;      // 0..1  (M)
    const int wn   = tid >> 6;            // 0..3  (N)
    const int row0 = blockIdx.y * 128, col0 = blockIdx.x * 128;
    const int NT   = K >> 5;

    float acc[4][4][4];
#pragma unroll
    for (int i = 0; i < 4; i++)
#pragma unroll
        for (int j = 0; j < 4; j++)
#pragma unroll
            for (int r = 0; r < 4; r++) acc[i][j][r] = 0.f;

    // ---- stage loader: 4 arrays x 128 rows x 64B (4 chunks of 16B) ----
    auto load_stage = [&](int kt, int stg) {
        const int k0 = kt << 5;
        const uint32_t sd = sb + stg * GSTAGE;
#pragma unroll
        for (int c = tid; c < 512; c += 256) {
            const int r = c >> 2, seg = c & 3;
            const uint32_t d = sd + r * 80 + seg * 16;
            const size_t ga = (size_t)(row0 + r) * K + k0 + seg * 8;
            const size_t gb = (size_t)(col0 + r) * K + k0 + seg * 8;
            CP16(d,             Ah_ + ga);
            CP16(d + GTILE,     Al_ + ga);
            CP16(d + 2 * GTILE, Bh_ + gb);
            CP16(d + 3 * GTILE, Bl_ + gb);
        }
    };

    load_stage(0, 0); CP_COMMIT();
    load_stage(1, 1); CP_COMMIT();

    // per-thread ldmatrix addresses (element offsets; *2 for bytes)
    const uint32_t aoff = (uint32_t)(((wm * 64 + (lane & 15)) * GLDA
                                      + ((lane >> 4) << 3)) * 2);
    const uint32_t boff = (uint32_t)(((wn * 32 + ((lane >> 4) << 3) + (lane & 7)) * GLDA
                                      + (((lane >> 3) & 1) << 3)) * 2);

    for (int kt = 0; kt < NT; kt++) {
        CP_WAIT(1);
        __syncthreads();

        const uint32_t sA = sb + (kt & 1) * GSTAGE;
#pragma unroll
        for (int ks = 0; ks < 2; ks++) {
            uint32_t ah[4][4], al[4][4], bh[2][4], bl[2][4];
            const uint32_t kb = (uint32_t)(ks * 32);   // 16 elems * 2B
#pragma unroll
            for (int mt = 0; mt < 4; mt++) {
                const uint32_t a = sA + aoff + (uint32_t)(mt * 16 * GLDA * 2) + kb;
                LDM_X4(ah[mt], a);
                LDM_X4(al[mt], a + GTILE);
            }
#pragma unroll
            for (int p = 0; p < 2; p++) {
                const uint32_t b = sA + 2 * GTILE + boff
                                 + (uint32_t)(p * 16 * GLDA * 2) + kb;
                LDM_X4(bh[p], b);
                LDM_X4(bl[p], b + GTILE);
            }
#pragma unroll
            for (int mt = 0; mt < 4; mt++)
#pragma unroll
                for (int nt = 0; nt < 4; nt++) {
                    const int p = nt >> 1, o = (nt & 1) * 2;
                    MMA16816(acc[mt][nt], ah[mt], bh[p][o],     bh[p][o + 1]);
                    MMA16816(acc[mt][nt], ah[mt], bl[p][o],     bl[p][o + 1]);
                    MMA16816(acc[mt][nt], al[mt], bh[p][o],     bh[p][o + 1]);
                }
        }
        __syncthreads();
        if (kt + 2 < NT) load_stage(kt + 2, kt & 1);
        CP_COMMIT();
    }
    CP_WAIT(0);

    // ---- epilogue straight from registers ----
#pragma unroll
    for (int mt = 0; mt < 4; mt++) {
#pragma unroll
        for (int nt = 0; nt < 4; nt++) {
            const int row = row0 + wm * 64 + mt * 16 + (lane >> 2);
            const int col = col0 + wn * 32 + nt * 8 + (lane & 3) * 2;
            const float b0 = __ldg(bias + col), b1 = __ldg(bias + col + 1);
#pragma unroll
            for (int half = 0; half < 2; half++) {
                const int rr = row + half * 8;
                float v0 = acc[mt][nt][half * 2]     + b0;
                float v1 = acc[mt][nt][half * 2 + 1] + b1;
                if (EPI == 0) {
                    *(float2*)&Cf[(size_t)rr * N + col] = make_float2(v0, v1);
                } else if (EPI == 1) {
                    const int b_ = rr >> 10, s = rr & 1023;
                    const int h  = col >> 6, d = col & 63;
                    *(float2*)&Cf[(((size_t)(b_ * NHEADS + h)) * SEQ + s) * DHEAD + d] =
                        make_float2(v0, v1);
                } else {
                    v0 = fmaxf(v0, 0.f); v1 = fmaxf(v1, 0.f);
                    bf16 h0 = __float2bfloat16(v0), h1 = __float2bfloat16(v1);
                    bf16 l0 = __float2bfloat16(v0 - __bfloat162float(h0));
                    bf16 l1 = __float2bfloat16(v1 - __bfloat162float(h1));
                    __nv_bfloat162 hp; hp.x = h0; hp.y = h1;
                    __nv_bfloat162 lp; lp.x = l0; lp.y = l1;
                    *(__nv_bfloat162*)&Ch[(size_t)rr * N + col] = hp;
                    *(__nv_bfloat162*)&Cl[(size_t)rr * N + col] = lp;
                }
            }
        }
    }
}

// ---------------------- fp32 -> bf16 hi/lo split -----------------------------
__global__ void __launch_bounds__(256)
split_kernel(const float* __restrict__ src, bf16* __restrict__ hi,
             bf16* __restrict__ lo, int n)
{
    int i0 = (blockIdx.x * 256 + threadIdx.x) * 4;
    if (i0 >= n) return;
#pragma unroll
    for (int j = 0; j < 4; j++) {
        float v = src[i0 + j];
        bf16 h = __float2bfloat16(v);
        hi[i0 + j] = h;
        lo[i0 + j] = __float2bfloat16(v - __bfloat162float(h));
    }
}

// ------------- weight transpose + split: src[K,N] -> dst[N,K] ---------------
__global__ void __launch_bounds__(256)
wtrans_kernel(const float* __restrict__ src, bf16* __restrict__ dh,
              bf16* __restrict__ dl, int K, int N)
{
    __shared__ float t[32][33];
    const int bx = blockIdx.x * 32;   // N
    const int by = blockIdx.y * 32;   // K
    const int tx = threadIdx.x, ty = threadIdx.y;
#pragma unroll
    for (int i = 0; i < 32; i += 8)
        t[ty + i][tx] = src[(size_t)(by + ty + i) * N + bx + tx];
    __syncthreads();
#pragma unroll
    for (int i = 0; i < 32; i += 8) {
        float v = t[tx][ty + i];
        bf16 h = __float2bfloat16(v);
        size_t o = (size_t)(bx + ty + i) * K + by + tx;
        dh[o] = h;
        dl[o] = __float2bfloat16(v - __bfloat162float(h));
    }
}

// ---------------------------- attention -------------------------------------
#define QSTR 68
#define KSTR 68
#define VSTR 64
#define ATT_SMEM ((64*QSTR + 64*KSTR + 64*VSTR) * 4)

__global__ void __launch_bounds__(256)
attn_kernel(const float* __restrict__ Q, const float* __restrict__ K,
            const float* __restrict__ V, bf16* __restrict__ ch,
            bf16* __restrict__ cl)
{
    extern __shared__ float sm[];
    float* Qs = sm;
    float* Ks = sm + 64 * QSTR;
    float* Vs = Ks + 64 * KSTR;

    const int qt = blockIdx.x;
    const int bh = blockIdx.y;
    const int t  = threadIdx.x;
    const int r  = t >> 2;
    const int c  = t & 3;
    const int q0 = qt * 64;
    const float scale = 0.125f;

    const float* Qg = Q + ((size_t)bh * SEQ + q0) * DHEAD;
    for (int i = t; i < 64 * 16; i += 256) {
        int row = i >> 4, dp = (i & 15) << 2;
        *(float4*)(&Qs[row * QSTR + dp]) = *(const float4*)(Qg + row * DHEAD + dp);
    }

    float m = -INFINITY, l = 0.f;
    float o[16];
#pragma unroll
    for (int i = 0; i < 16; i++) o[i] = 0.f;
    const int qg = q0 + r;

    for (int kt = 0; kt <= qt; kt++) {
        const float* Kg = K + ((size_t)bh * SEQ + kt * 64) * DHEAD;
        const float* Vg = V + ((size_t)bh * SEQ + kt * 64) * DHEAD;

        __syncthreads();
        for (int i = t; i < 64 * 16; i += 256) {
            int row = i >> 4, dp = (i & 15) << 2;
            *(float4*)(&Ks[row * KSTR + dp]) = *(const float4*)(Kg + row * DHEAD + dp);
            *(float4*)(&Vs[row * VSTR + dp]) = *(const float4*)(Vg + row * DHEAD + dp);
        }
        __syncthreads();

        float s[16];
#pragma unroll
        for (int jj = 0; jj < 16; jj++) s[jj] = 0.f;
        for (int d = 0; d < 64; d++) {
            float qv = Qs[r * QSTR + d];
#pragma unroll
            for (int jj = 0; jj < 16; jj++)
                s[jj] += qv * Ks[(c + 4 * jj) * KSTR + d];
        }
#pragma unroll
        for (int jj = 0; jj < 16; jj++) {
            int jgl = kt * 64 + c + 4 * jj;
            s[jj] = s[jj] * scale + (jgl > qg ? -1e9f : 0.f);
        }

        float tm = s[0];
#pragma unroll
        for (int jj = 1; jj < 16; jj++) tm = fmaxf(tm, s[jj]);
        tm = fmaxf(tm, __shfl_xor_sync(0xffffffffu, tm, 1));
        tm = fmaxf(tm, __shfl_xor_sync(0xffffffffu, tm, 2));

        float mnew  = fmaxf(m, tm);
        float alpha = __expf(m - mnew);
        float psum  = 0.f;
#pragma unroll
        for (int jj = 0; jj < 16; jj++) {
            s[jj] = __expf(s[jj] - mnew);
            psum += s[jj];
        }
        psum += __shfl_xor_sync(0xffffffffu, psum, 1);
        psum += __shfl_xor_sync(0xffffffffu, psum, 2);
        l = l * alpha + psum;
        m = mnew;
#pragma unroll
        for (int dd = 0; dd < 16; dd++) o[dd] *= alpha;

        __syncthreads();
#pragma unroll
        for (int jj = 0; jj < 16; jj++)
            Ks[r * KSTR + c + 4 * jj] = s[jj];
        __syncthreads();

        for (int j2 = 0; j2 < 64; j2++) {
            float pv = Ks[r * KSTR + j2];
#pragma unroll
            for (int dd = 0; dd < 16; dd++)
                o[dd] += pv * Vs[j2 * VSTR + c + 4 * dd];
        }
    }

    const float inv = 1.f / l;
    const int b_ = bh / NHEADS, h = bh % NHEADS;
    size_t base = ((size_t)(b_ * SEQ + qg)) * DMODEL + h * DHEAD;
#pragma unroll
    for (int dd = 0; dd < 16; dd++) {
        float v = o[dd] * inv;
        bf16 hi = __float2bfloat16(v);
        ch[base + c + 4 * dd] = hi;
        cl[base + c + 4 * dd] = __float2bfloat16(v - __bfloat162float(hi));
    }
}

// ----------------------- fused residual add + LayerNorm ---------------------
template<bool HILO>
__global__ void __launch_bounds__(256)
add_ln_kernel(const float* __restrict__ a, const float* __restrict__ b,
              const float* __restrict__ g, const float* __restrict__ be,
              float* __restrict__ out, bf16* __restrict__ ohi, bf16* __restrict__ olo)
{
    __shared__ float red[8];
    const int row = blockIdx.x;
    const int t   = threadIdx.x;
    const float* ar = a + (size_t)row * DMODEL;
    const float* br = b + (size_t)row * DMODEL;

    float v0 = ar[t]       + br[t];
    float v1 = ar[t + 256] + br[t + 256];
    float v2 = ar[t + 512] + br[t + 512];

    float sum = v0 + v1 + v2;
#pragma unroll
    for (int off = 16; off; off >>= 1) sum += __shfl_xor_sync(0xffffffffu, sum, off);
    if ((t & 31) == 0) red[t >> 5] = sum;
    __syncthreads();
    float tot = 0.f;
#pragma unroll
    for (int w = 0; w < 8; w++) tot += red[w];
    const float mu = tot * (1.f / DMODEL);
    __syncthreads();

    float d0 = v0 - mu, d1 = v1 - mu, d2 = v2 - mu;
    float vs = d0 * d0 + d1 * d1 + d2 * d2;
#pragma unroll
    for (int off = 16; off; off >>= 1) vs += __shfl_xor_sync(0xffffffffu, vs, off);
    if ((t & 31) == 0) red[t >> 5] = vs;
    __syncthreads();
    tot = 0.f;
#pragma unroll
    for (int w = 0; w < 8; w++) tot += red[w];
    const float rstd = rsqrtf(tot * (1.f / DMODEL) + 1e-6f);

    float* o = out + (size_t)row * DMODEL;
    float r0 = g[t]       * d0 * rstd + be[t];
    float r1 = g[t + 256] * d1 * rstd + be[t + 256];
    float r2 = g[t + 512] * d2 * rstd + be[t + 512];
    o[t] = r0; o[t + 256] = r1; o[t + 512] = r2;
    if (HILO) {
        size_t base = (size_t)row * DMODEL;
#pragma unroll
        for (int j = 0; j < 3; j++) {
            float v = j == 0 ? r0 : (j == 1 ? r1 : r2);
            int idx = t + j * 256;
            bf16 h = __float2bfloat16(v);
            ohi[base + idx] = h;
            olo[base + idx] = __float2bfloat16(v - __bfloat162float(h));
        }
    }
}

// --------------------------------- launch ------------------------------------
extern "C" void kernel_launch(void* const* d_in, const int* in_sizes, int n_in,
                              void* d_out, int out_size)
{
    const float* x  = (const float*)d_in[0];
    const float* wq = (const float*)d_in[2];
    const float* bq = (const float*)d_in[3];
    const float* wk = (const float*)d_in[4];
    const float* bk = (const float*)d_in[5];
    const float* wv = (const float*)d_in[6];
    const float* bv = (const float*)d_in[7];
    const float* wo = (const float*)d_in[8];
    const float* bo = (const float*)d_in[9];
    const float* w1 = (const float*)d_in[10];
    const float* b1 = (const float*)d_in[11];
    const float* w2 = (const float*)d_in[12];
    const float* b2 = (const float*)d_in[13];
    const float* g1 = (const float*)d_in[14];
    const float* be1= (const float*)d_in[15];
    const float* g2 = (const float*)d_in[16];
    const float* be2= (const float*)d_in[17];
    float* out = (float*)d_out;

    bf16 *xh,*xl,*wqh,*wql,*wkh,*wkl,*wvh,*wvl,*woh,*wol,*w1h,*w1l,*w2h,*w2l;
    bf16 *ch,*cl,*o1h,*o1l,*h1h,*h1l;
    float *q,*k,*v,*attn,*out1,*ffn;
    cudaGetSymbolAddress((void**)&xh, g_xh);   cudaGetSymbolAddress((void**)&xl, g_xl);
    cudaGetSymbolAddress((void**)&wqh,g_wqh);  cudaGetSymbolAddress((void**)&wql,g_wql);
    cudaGetSymbolAddress((void**)&wkh,g_wkh);  cudaGetSymbolAddress((void**)&wkl,g_wkl);
    cudaGetSymbolAddress((void**)&wvh,g_wvh);  cudaGetSymbolAddress((void**)&wvl,g_wvl);
    cudaGetSymbolAddress((void**)&woh,g_woh);  cudaGetSymbolAddress((void**)&wol,g_wol);
    cudaGetSymbolAddress((void**)&w1h,g_w1h);  cudaGetSymbolAddress((void**)&w1l,g_w1l);
    cudaGetSymbolAddress((void**)&w2h,g_w2h);  cudaGetSymbolAddress((void**)&w2l,g_w2l);
    cudaGetSymbolAddress((void**)&ch, g_ch);   cudaGetSymbolAddress((void**)&cl, g_cl);
    cudaGetSymbolAddress((void**)&o1h,g_o1h);  cudaGetSymbolAddress((void**)&o1l,g_o1l);
    cudaGetSymbolAddress((void**)&h1h,g_h1h);  cudaGetSymbolAddress((void**)&h1l,g_h1l);
    cudaGetSymbolAddress((void**)&q,  g_q);    cudaGetSymbolAddress((void**)&k,  g_k);
    cudaGetSymbolAddress((void**)&v,  g_v);    cudaGetSymbolAddress((void**)&attn,g_attn);
    cudaGetSymbolAddress((void**)&out1,g_out1);cudaGetSymbolAddress((void**)&ffn, g_ffn);

    cudaFuncSetAttribute(mma_gemm<0>, cudaFuncAttributeMaxDynamicSharedMemorySize, GSMEM);
    cudaFuncSetAttribute(mma_gemm<1>, cudaFuncAttributeMaxDynamicSharedMemorySize, GSMEM);
    cudaFuncSetAttribute(mma_gemm<2>, cudaFuncAttributeMaxDynamicSharedMemorySize, GSMEM);
    cudaFuncSetAttribute(attn_kernel, cudaFuncAttributeMaxDynamicSharedMemorySize, ATT_SMEM);

    // ---- prep: split x, transpose+split weights ----
    split_kernel<<<MROWS * DMODEL / 1024, 256>>>(x, xh, xl, MROWS * DMODEL);
    dim3 tb(32, 8);
    wtrans_kernel<<<dim3(DMODEL/32, DMODEL/32), tb>>>(wq, wqh, wql, DMODEL, DMODEL);
    wtrans_kernel<<<dim3(DMODEL/32, DMODEL/32), tb>>>(wk, wkh, wkl, DMODEL, DMODEL);
    wtrans_kernel<<<dim3(DMODEL/32, DMODEL/32), tb>>>(wv, wvh, wvl, DMODEL, DMODEL);
    wtrans_kernel<<<dim3(DMODEL/32, DMODEL/32), tb>>>(wo, woh, wol, DMODEL, DMODEL);
    wtrans_kernel<<<dim3(DFF/32,    DMODEL/32), tb>>>(w1, w1h, w1l, DMODEL, DFF);
    wtrans_kernel<<<dim3(DMODEL/32, DFF/32),    tb>>>(w2, w2h, w2l, DFF, DMODEL);

    // ---- QKV ----
    dim3 gQ(DMODEL/128, MROWS/128);   // (6,64)
    mma_gemm<1><<<gQ, 256, GSMEM>>>(xh, xl, wqh, wql, bq, q, nullptr, nullptr, DMODEL, DMODEL);
    mma_gemm<1><<<gQ, 256, GSMEM>>>(xh, xl, wkh, wkl, bk, k, nullptr, nullptr, DMODEL, DMODEL);
    mma_gemm<1><<<gQ, 256, GSMEM>>>(xh, xl, wvh, wvl, bv, v, nullptr, nullptr, DMODEL, DMODEL);

    // ---- attention ----
    attn_kernel<<<dim3(SEQ/64, BATCH*NHEADS), 256, ATT_SMEM>>>(q, k, v, ch, cl);

    // ---- O proj + LN1 ----
    mma_gemm<0><<<gQ, 256, GSMEM>>>(ch, cl, woh, wol, bo, attn, nullptr, nullptr, DMODEL, DMODEL);
    add_ln_kernel<true><<<MROWS, 256>>>(x, attn, g1, be1, out1, o1h, o1l);

    // ---- FFN ----
    mma_gemm<2><<<dim3(DFF/128, MROWS/128), 256, GSMEM>>>(o1h, o1l, w1h, w1l, b1,
                                                          nullptr, h1h, h1l, DFF, DMODEL);
    mma_gemm<0><<<gQ, 256, GSMEM>>>(h1h, h1l, w2h, w2l, b2, ffn, nullptr, nullptr, DMODEL, DFF);
    add_ln_kernel<false><<<MROWS, 256>>>(out1, ffn, g2, be2, out, nullptr, nullptr);
}

// round 4
// speedup vs baseline: 3.1161x; 1.6563x over previous
#include <cuda_runtime.h>
#include <cuda_bf16.h>
#include <math.h>
#include <stdint.h>

// ---------------------------------------------------------------------------
// DecoderLayer on GB300 (compute_100 PTX -> mma.sync HMMA everywhere).
// bf16 3-split GEMMs + bf16 3-split flash attention. fp32 LN.
// B=8, S=1024, D=768, H=12, Dh=64, DFF=3072.
// ---------------------------------------------------------------------------
#define BATCH   8
#define SEQ     1024
#define DMODEL  768
#define NHEADS  12
#define DHEAD   64
#define DFF     3072
#define MROWS   (BATCH*SEQ)          // 8192

typedef __nv_bfloat16 bf16;

// ------------------------- scratch (device globals) -------------------------
__device__ bf16  g_xh  [MROWS*DMODEL],   g_xl  [MROWS*DMODEL];
__device__ bf16  g_wqkvh[3*DMODEL*DMODEL], g_wqkvl[3*DMODEL*DMODEL]; // [2304,768]
__device__ bf16  g_woh [DMODEL*DMODEL],  g_wol [DMODEL*DMODEL];
__device__ bf16  g_w1h [DFF*DMODEL],     g_w1l [DFF*DMODEL];
__device__ bf16  g_w2h [DMODEL*DFF],     g_w2l [DMODEL*DFF];
__device__ float g_bqkv[3*DMODEL];
__device__ bf16  g_qkvh[3*MROWS*DMODEL], g_qkvl[3*MROWS*DMODEL];  // [which][b,h,s,d]
__device__ bf16  g_ch  [MROWS*DMODEL],   g_cl  [MROWS*DMODEL];    // ctx hi/lo
__device__ float g_attn[MROWS*DMODEL];
__device__ float g_out1[MROWS*DMODEL];
__device__ bf16  g_o1h [MROWS*DMODEL],   g_o1l [MROWS*DMODEL];
__device__ bf16  g_h1h [MROWS*DFF],      g_h1l [MROWS*DFF];
__device__ float g_ffn [MROWS*DMODEL];

// ------------------------------ PTX helpers ---------------------------------
__device__ __forceinline__ uint32_t smem_u32(const void* p) {
    uint32_t a;
    asm("{ .reg .u64 t; cvta.to.shared.u64 t, %1; cvt.u32.u64 %0, t; }"
        : "=r"(a) : "l"(p));
    return a;
}

#define CP16(dst, src) \
    asm volatile("cp.async.cg.shared.global [%0], [%1], 16;" \
                 :: "r"(dst), "l"(src))
#define CP_COMMIT() asm volatile("cp.async.commit_group;" ::: "memory")
#define CP_WAIT(n)  asm volatile("cp.async.wait_group %0;" :: "n"(n) : "memory")

#define LDM_X4(r, a) \
    asm volatile("ldmatrix.sync.aligned.m8n8.x4.shared.b16 {%0,%1,%2,%3}, [%4];" \
        : "=r"((r)[0]), "=r"((r)[1]), "=r"((r)[2]), "=r"((r)[3]) : "r"(a))

#define LDM_X4T(r, a) \
    asm volatile("ldmatrix.sync.aligned.m8n8.x4.trans.shared.b16 {%0,%1,%2,%3}, [%4];" \
        : "=r"((r)[0]), "=r"((r)[1]), "=r"((r)[2]), "=r"((r)[3]) : "r"(a))

#define MMA16816(d, a, b0, b1) \
    asm volatile("mma.sync.aligned.m16n8k16.row.col.f32.bf16.bf16.f32 " \
        "{%0,%1,%2,%3}, {%4,%5,%6,%7}, {%8,%9}, {%0,%1,%2,%3};" \
        : "+f"((d)[0]), "+f"((d)[1]), "+f"((d)[2]), "+f"((d)[3]) \
        : "r"((a)[0]), "r"((a)[1]), "r"((a)[2]), "r"((a)[3]), "r"(b0), "r"(b1))

__device__ __forceinline__ void split2(float x, float y, uint32_t& hp, uint32_t& lp) {
    __nv_bfloat162 h = __float22bfloat162_rn(make_float2(x, y));
    float2 r = make_float2(x - __bfloat162float(h.x), y - __bfloat162float(h.y));
    __nv_bfloat162 l = __float22bfloat162_rn(r);
    hp = *(uint32_t*)&h;
    lp = *(uint32_t*)&l;
}

// ---------------------- HMMA GEMM: C = A @ B^T + bias -----------------------
// BM=BN=128, BK=32. 256 threads = 8 warps (2 x 4), warp tile 64x32.
// EPI: 0 = fp32 [M,N]; 2 = ReLU + bf16 hi/lo [M,N]; 3 = QKV bf16 hi/lo scatter.
#define GLDA   40
#define GTILE  (128 * GLDA * 2)      // 10240 B
#define GSTAGE (4 * GTILE)
#define GSMEM  (2 * GSTAGE)          // 81920 B

template<int EPI>
__global__ void __launch_bounds__(256, 1)
mma_gemm(const bf16* __restrict__ Ah_, const bf16* __restrict__ Al_,
         const bf16* __restrict__ Bh_, const bf16* __restrict__ Bl_,
         const float* __restrict__ bias,
         float* __restrict__ Cf, bf16* __restrict__ Ch, bf16* __restrict__ Cl,
         int N, int K)
{
    extern __shared__ __align__(128) char smem[];
    const uint32_t sb = smem_u32(smem);
    const int tid  = threadIdx.x;
    const int lane = tid & 31;
    const int wm   = (tid >> 5) & 1;
    const int wn   = tid >> 6;
    const int row0 = blockIdx.y * 128, col0 = blockIdx.x * 128;
    const int NT   = K >> 5;

    float acc[4][4][4];
#pragma unroll
    for (int i = 0; i < 4; i++)
#pragma unroll
        for (int j = 0; j < 4; j++)
#pragma unroll
            for (int r = 0; r < 4; r++) acc[i][j][r] = 0.f;

    auto load_stage = [&](int kt, int stg) {
        const int k0 = kt << 5;
        const uint32_t sd = sb + stg * GSTAGE;
#pragma unroll
        for (int c = tid; c < 512; c += 256) {
            const int r = c >> 2, seg = c & 3;
            const uint32_t d = sd + r * 80 + seg * 16;
            const size_t ga = (size_t)(row0 + r) * K + k0 + seg * 8;
            const size_t gb = (size_t)(col0 + r) * K + k0 + seg * 8;
            CP16(d,             Ah_ + ga);
            CP16(d + GTILE,     Al_ + ga);
            CP16(d + 2 * GTILE, Bh_ + gb);
            CP16(d + 3 * GTILE, Bl_ + gb);
        }
    };

    load_stage(0, 0); CP_COMMIT();
    load_stage(1, 1); CP_COMMIT();

    const uint32_t aoff = (uint32_t)(((wm * 64 + (lane & 15)) * GLDA
                                      + ((lane >> 4) << 3)) * 2);
    const uint32_t boff = (uint32_t)(((wn * 32 + ((lane >> 4) << 3) + (lane & 7)) * GLDA
                                      + (((lane >> 3) & 1) << 3)) * 2);

    for (int kt = 0; kt < NT; kt++) {
        CP_WAIT(1);
        __syncthreads();

        const uint32_t sA = sb + (kt & 1) * GSTAGE;
#pragma unroll
        for (int ks = 0; ks < 2; ks++) {
            uint32_t ah[4][4], al[4][4], bh[2][4], bl[2][4];
            const uint32_t kb = (uint32_t)(ks * 32);
#pragma unroll
            for (int mt = 0; mt < 4; mt++) {
                const uint32_t a = sA + aoff + (uint32_t)(mt * 16 * GLDA * 2) + kb;
                LDM_X4(ah[mt], a);
                LDM_X4(al[mt], a + GTILE);
            }
#pragma unroll
            for (int p = 0; p < 2; p++) {
                const uint32_t b = sA + 2 * GTILE + boff
                                 + (uint32_t)(p * 16 * GLDA * 2) + kb;
                LDM_X4(bh[p], b);
                LDM_X4(bl[p], b + GTILE);
            }
#pragma unroll
            for (int mt = 0; mt < 4; mt++)
#pragma unroll
                for (int nt = 0; nt < 4; nt++) {
                    const int p = nt >> 1, o = (nt & 1) * 2;
                    MMA16816(acc[mt][nt], ah[mt], bh[p][o], bh[p][o + 1]);
                    MMA16816(acc[mt][nt], ah[mt], bl[p][o], bl[p][o + 1]);
                    MMA16816(acc[mt][nt], al[mt], bh[p][o], bh[p][o + 1]);
                }
        }
        __syncthreads();
        if (kt + 2 < NT) load_stage(kt + 2, kt & 1);
        CP_COMMIT();
    }
    CP_WAIT(0);

#pragma unroll
    for (int mt = 0; mt < 4; mt++) {
#pragma unroll
        for (int nt = 0; nt < 4; nt++) {
            const int row = row0 + wm * 64 + mt * 16 + (lane >> 2);
            const int col = col0 + wn * 32 + nt * 8 + (lane & 3) * 2;
            const float b0 = __ldg(bias + col), b1 = __ldg(bias + col + 1);
#pragma unroll
            for (int half = 0; half < 2; half++) {
                const int rr = row + half * 8;
                float v0 = acc[mt][nt][half * 2]     + b0;
                float v1 = acc[mt][nt][half * 2 + 1] + b1;
                if (EPI == 0) {
                    *(float2*)&Cf[(size_t)rr * N + col] = make_float2(v0, v1);
                } else if (EPI == 2) {
                    v0 = fmaxf(v0, 0.f); v1 = fmaxf(v1, 0.f);
                    uint32_t hp, lp;
                    split2(v0, v1, hp, lp);
                    *(uint32_t*)&Ch[(size_t)rr * N + col] = hp;
                    *(uint32_t*)&Cl[(size_t)rr * N + col] = lp;
                } else {  // EPI==3: QKV scatter [which][b,h,s,d], Q pre-scaled
                    const int which = col / DMODEL;
                    const int cc = col - which * DMODEL;
                    const int h = cc >> 6, d = cc & 63;
                    if (which == 0) { v0 *= 0.125f; v1 *= 0.125f; }
                    const int b_ = rr >> 10, s = rr & 1023;
                    const size_t dst = (size_t)which * MROWS * DMODEL
                        + (((size_t)(b_ * NHEADS + h)) * SEQ + s) * DHEAD + d;
                    uint32_t hp, lp;
                    split2(v0, v1, hp, lp);
                    *(uint32_t*)&Ch[dst] = hp;
                    *(uint32_t*)&Cl[dst] = lp;
                }
            }
        }
    }
}

// ---------------------- flash attention (HMMA bf16 3-split) ------------------
// BQ=BK=64, 128 threads = 4 warps, each warp 16 q-rows.
// Smem: Q hi/lo [64][72] + 2 stages of (Kh,Kl,Vh,Vl)[64][72].
#define ASTR   72
#define ATILE  (64 * ASTR * 2)        // 9216 B
#define AKVST  (4 * ATILE)            // 36864 B
#define ATT_SMEM (2 * ATILE + 2 * AKVST)   // 92160 B

__global__ void __launch_bounds__(128, 1)
attn_mma(const bf16* __restrict__ QKVh, const bf16* __restrict__ QKVl,
         bf16* __restrict__ ch, bf16* __restrict__ cl)
{
    extern __shared__ __align__(128) char smem[];
    const uint32_t sb = smem_u32(smem);
    const int tid = threadIdx.x, lane = tid & 31, wid = tid >> 5;
    const int qt = blockIdx.x, bh = blockIdx.y, q0 = qt * 64;
    constexpr size_t MD = (size_t)MROWS * DMODEL;
    const bf16 *Qh = QKVh,        *Kh = QKVh + MD, *Vh = QKVh + 2 * MD;
    const bf16 *Ql = QKVl,        *Kl = QKVl + MD, *Vl = QKVl + 2 * MD;
    const size_t hb = (size_t)bh * SEQ * DHEAD;

    auto load_kv = [&](int kt, int stg) {
        const size_t gb = hb + (size_t)(kt * 64) * 64;
        const uint32_t sd = sb + 2 * ATILE + stg * AKVST;
        for (int i = tid; i < 512; i += 128) {
            const int row = i >> 3, seg = i & 7;
            const uint32_t d0 = sd + row * 144 + seg * 16;
            const size_t g = gb + row * 64 + seg * 8;
            CP16(d0,             Kh + g);
            CP16(d0 + ATILE,     Kl + g);
            CP16(d0 + 2 * ATILE, Vh + g);
            CP16(d0 + 3 * ATILE, Vl + g);
        }
    };

    {   // Q tiles + stage0
        const size_t gq = hb + (size_t)q0 * 64;
        for (int i = tid; i < 512; i += 128) {
            const int row = i >> 3, seg = i & 7;
            const uint32_t d0 = sb + row * 144 + seg * 16;
            const size_t g = gq + row * 64 + seg * 8;
            CP16(d0,         Qh + g);
            CP16(d0 + ATILE, Ql + g);
        }
        load_kv(0, 0);
    }
    CP_COMMIT();
    load_kv(qt >= 1 ? 1 : 0, 1);   // keep group non-empty
    CP_COMMIT();

    uint32_t qh[4][4], ql[4][4];
    float oacc[8][4];
#pragma unroll
    for (int nt = 0; nt < 8; nt++)
#pragma unroll
        for (int e = 0; e < 4; e++) oacc[nt][e] = 0.f;
    float m0 = -1e30f, m1 = -1e30f, l0 = 0.f, l1 = 0.f;

    const int lcol  = (lane & 3) * 2;
    const int rowg0 = q0 + wid * 16 + (lane >> 2);

    for (int kt = 0; kt <= qt; kt++) {
        CP_WAIT(1);
        __syncthreads();
        if (kt == 0) {
#pragma unroll
            for (int kc = 0; kc < 4; kc++) {
                const uint32_t a = sb + (uint32_t)(((wid * 16 + (lane & 15)) * ASTR
                                    + ((lane >> 4) << 3) + kc * 16) * 2);
                LDM_X4(qh[kc], a);
                LDM_X4(ql[kc], a + ATILE);
            }
        }
        const uint32_t kvb = sb + 2 * ATILE + (kt & 1) * AKVST;

        float sacc[8][4];
#pragma unroll
        for (int nt = 0; nt < 8; nt++)
#pragma unroll
            for (int e = 0; e < 4; e++) sacc[nt][e] = 0.f;

#pragma unroll
        for (int kc = 0; kc < 4; kc++) {
            uint32_t kh2[8][2], kl2[8][2];
#pragma unroll
            for (int g = 0; g < 4; g++) {
                const uint32_t a = kvb + (uint32_t)(((g * 16 + ((lane >> 4) << 3)
                    + (lane & 7)) * ASTR + (((lane >> 3) & 1) << 3) + kc * 16) * 2);
                uint32_t r[4];
                LDM_X4(r, a);
                kh2[2*g][0]=r[0]; kh2[2*g][1]=r[1]; kh2[2*g+1][0]=r[2]; kh2[2*g+1][1]=r[3];
                LDM_X4(r, a + ATILE);
                kl2[2*g][0]=r[0]; kl2[2*g][1]=r[1]; kl2[2*g+1][0]=r[2]; kl2[2*g+1][1]=r[3];
            }
#pragma unroll
            for (int nt = 0; nt < 8; nt++) {
                MMA16816(sacc[nt], qh[kc], kh2[nt][0], kh2[nt][1]);
                MMA16816(sacc[nt], qh[kc], kl2[nt][0], kl2[nt][1]);
                MMA16816(sacc[nt], ql[kc], kh2[nt][0], kh2[nt][1]);
            }
        }

        if (kt == qt) {   // causal mask on diagonal tile
#pragma unroll
            for (int nt = 0; nt < 8; nt++) {
                const int colb = kt * 64 + nt * 8 + lcol;
                if (colb     > rowg0)     sacc[nt][0] = -1e30f;
                if (colb + 1 > rowg0)     sacc[nt][1] = -1e30f;
                if (colb     > rowg0 + 8) sacc[nt][2] = -1e30f;
                if (colb + 1 > rowg0 + 8) sacc[nt][3] = -1e30f;
            }
        }

        float tm0 = -1e30f, tm1 = -1e30f;
#pragma unroll
        for (int nt = 0; nt < 8; nt++) {
            tm0 = fmaxf(tm0, fmaxf(sacc[nt][0], sacc[nt][1]));
            tm1 = fmaxf(tm1, fmaxf(sacc[nt][2], sacc[nt][3]));
        }
        tm0 = fmaxf(tm0, __shfl_xor_sync(0xffffffffu, tm0, 1));
        tm0 = fmaxf(tm0, __shfl_xor_sync(0xffffffffu, tm0, 2));
        tm1 = fmaxf(tm1, __shfl_xor_sync(0xffffffffu, tm1, 1));
        tm1 = fmaxf(tm1, __shfl_xor_sync(0xffffffffu, tm1, 2));

        const float mn0 = fmaxf(m0, tm0), mn1 = fmaxf(m1, tm1);
        const float a0 = __expf(m0 - mn0), a1 = __expf(m1 - mn1);
        m0 = mn0; m1 = mn1;

        float s0 = 0.f, s1 = 0.f;
#pragma unroll
        for (int nt = 0; nt < 8; nt++) {
            sacc[nt][0] = __expf(sacc[nt][0] - mn0); s0 += sacc[nt][0];
            sacc[nt][1] = __expf(sacc[nt][1] - mn0); s0 += sacc[nt][1];
            sacc[nt][2] = __expf(sacc[nt][2] - mn1); s1 += sacc[nt][2];
            sacc[nt][3] = __expf(sacc[nt][3] - mn1); s1 += sacc[nt][3];
        }
        s0 += __shfl_xor_sync(0xffffffffu, s0, 1);
        s0 += __shfl_xor_sync(0xffffffffu, s0, 2);
        s1 += __shfl_xor_sync(0xffffffffu, s1, 1);
        s1 += __shfl_xor_sync(0xffffffffu, s1, 2);
        l0 = l0 * a0 + s0;
        l1 = l1 * a1 + s1;
#pragma unroll
        for (int nt = 0; nt < 8; nt++) {
            oacc[nt][0] *= a0; oacc[nt][1] *= a0;
            oacc[nt][2] *= a1; oacc[nt][3] *= a1;
        }

        const uint32_t vb = kvb + 2 * ATILE;
#pragma unroll
        for (int j = 0; j < 4; j++) {
            uint32_t vh2[8][2], vl2[8][2];
#pragma unroll
            for (int ng = 0; ng < 4; ng++) {
                const uint32_t a = vb + (uint32_t)(((j * 16 + (lane & 15)) * ASTR
                                    + ng * 16 + ((lane >> 4) << 3)) * 2);
                uint32_t r[4];
                LDM_X4T(r, a);
                vh2[2*ng][0]=r[0]; vh2[2*ng][1]=r[1]; vh2[2*ng+1][0]=r[2]; vh2[2*ng+1][1]=r[3];
                LDM_X4T(r, a + ATILE);
                vl2[2*ng][0]=r[0]; vl2[2*ng][1]=r[1]; vl2[2*ng+1][0]=r[2]; vl2[2*ng+1][1]=r[3];
            }
            uint32_t ph[4], pl[4];
            split2(sacc[2*j][0],   sacc[2*j][1],   ph[0], pl[0]);
            split2(sacc[2*j][2],   sacc[2*j][3],   ph[1], pl[1]);
            split2(sacc[2*j+1][0], sacc[2*j+1][1], ph[2], pl[2]);
            split2(sacc[2*j+1][2], sacc[2*j+1][3], ph[3], pl[3]);
#pragma unroll
            for (int nt = 0; nt < 8; nt++) {
                MMA16816(oacc[nt], ph, vh2[nt][0], vh2[nt][1]);
                MMA16816(oacc[nt], ph, vl2[nt][0], vl2[nt][1]);
                MMA16816(oacc[nt], pl, vh2[nt][0], vh2[nt][1]);
            }
        }
        __syncthreads();
        if (kt + 2 <= qt) load_kv(kt + 2, kt & 1);
        CP_COMMIT();
    }

    const float i0 = 1.f / l0, i1 = 1.f / l1;
    const int b_ = bh / NHEADS, h = bh % NHEADS;
#pragma unroll
    for (int nt = 0; nt < 8; nt++) {
        const int d = nt * 8 + lcol;
        const size_t r0i = ((size_t)(b_ * SEQ + rowg0)) * DMODEL + h * 64 + d;
        const size_t r1i = r0i + (size_t)8 * DMODEL;
        uint32_t hp, lp;
        split2(oacc[nt][0] * i0, oacc[nt][1] * i0, hp, lp);
        *(uint32_t*)&ch[r0i] = hp;
        *(uint32_t*)&cl[r0i] = lp;
        split2(oacc[nt][2] * i1, oacc[nt][3] * i1, hp, lp);
        *(uint32_t*)&ch[r1i] = hp;
        *(uint32_t*)&cl[r1i] = lp;
    }
}

// ---------------------- prep kernels ----------------------------------------
__global__ void __launch_bounds__(256)
split_kernel(const float* __restrict__ src, bf16* __restrict__ hi,
             bf16* __restrict__ lo, int n)
{
    int i0 = (blockIdx.x * 256 + threadIdx.x) * 4;
    if (i0 >= n) return;
#pragma unroll
    for (int j = 0; j < 4; j++) {
        float v = src[i0 + j];
        bf16 h = __float2bfloat16(v);
        hi[i0 + j] = h;
        lo[i0 + j] = __float2bfloat16(v - __bfloat162float(h));
    }
}

__global__ void __launch_bounds__(256)
wtrans_kernel(const float* __restrict__ src, bf16* __restrict__ dh,
              bf16* __restrict__ dl, int K, int N)
{
    __shared__ float t[32][33];
    const int bx = blockIdx.x * 32;
    const int by = blockIdx.y * 32;
    const int tx = threadIdx.x, ty = threadIdx.y;
#pragma unroll
    for (int i = 0; i < 32; i += 8)
        t[ty + i][tx] = src[(size_t)(by + ty + i) * N + bx + tx];
    __syncthreads();
#pragma unroll
    for (int i = 0; i < 32; i += 8) {
        float v = t[tx][ty + i];
        bf16 h = __float2bfloat16(v);
        size_t o = (size_t)(bx + ty + i) * K + by + tx;
        dh[o] = h;
        dl[o] = __float2bfloat16(v - __bfloat162float(h));
    }
}

__global__ void __launch_bounds__(256)
concat_bias(const float* __restrict__ bq, const float* __restrict__ bk,
            const float* __restrict__ bv, float* __restrict__ out)
{
    int i = blockIdx.x * 256 + threadIdx.x;
    if (i >= 3 * DMODEL) return;
    out[i] = i < DMODEL ? bq[i] : (i < 2 * DMODEL ? bk[i - DMODEL] : bv[i - 2 * DMODEL]);
}

// ----------------------- fused residual add + LayerNorm ---------------------
template<bool HILO>
__global__ void __launch_bounds__(256)
add_ln_kernel(const float* __restrict__ a, const float* __restrict__ b,
              const float* __restrict__ g, const float* __restrict__ be,
              float* __restrict__ out, bf16* __restrict__ ohi, bf16* __restrict__ olo)
{
    __shared__ float red[8];
    const int row = blockIdx.x;
    const int t   = threadIdx.x;
    const float* ar = a + (size_t)row * DMODEL;
    const float* br = b + (size_t)row * DMODEL;

    float v0 = ar[t]       + br[t];
    float v1 = ar[t + 256] + br[t + 256];
    float v2 = ar[t + 512] + br[t + 512];

    float sum = v0 + v1 + v2;
#pragma unroll
    for (int off = 16; off; off >>= 1) sum += __shfl_xor_sync(0xffffffffu, sum, off);
    if ((t & 31) == 0) red[t >> 5] = sum;
    __syncthreads();
    float tot = 0.f;
#pragma unroll
    for (int w = 0; w < 8; w++) tot += red[w];
    const float mu = tot * (1.f / DMODEL);
    __syncthreads();

    float d0 = v0 - mu, d1 = v1 - mu, d2 = v2 - mu;
    float vs = d0 * d0 + d1 * d1 + d2 * d2;
#pragma unroll
    for (int off = 16; off; off >>= 1) vs += __shfl_xor_sync(0xffffffffu, vs, off);
    if ((t & 31) == 0) red[t >> 5] = vs;
    __syncthreads();
    tot = 0.f;
#pragma unroll
    for (int w = 0; w < 8; w++) tot += red[w];
    const float rstd = rsqrtf(tot * (1.f / DMODEL) + 1e-6f);

    float* o = out + (size_t)row * DMODEL;
    float r0 = g[t]       * d0 * rstd + be[t];
    float r1 = g[t + 256] * d1 * rstd + be[t + 256];
    float r2 = g[t + 512] * d2 * rstd + be[t + 512];
    o[t] = r0; o[t + 256] = r1; o[t + 512] = r2;
    if (HILO) {
        size_t base = (size_t)row * DMODEL;
#pragma unroll
        for (int j = 0; j < 3; j++) {
            float v = j == 0 ? r0 : (j == 1 ? r1 : r2);
            int idx = t + j * 256;
            bf16 h = __float2bfloat16(v);
            ohi[base + idx] = h;
            olo[base + idx] = __float2bfloat16(v - __bfloat162float(h));
        }
    }
}

// --------------------------------- launch ------------------------------------
extern "C" void kernel_launch(void* const* d_in, const int* in_sizes, int n_in,
                              void* d_out, int out_size)
{
    const float* x  = (const float*)d_in[0];
    const float* wq = (const float*)d_in[2];
    const float* bq = (const float*)d_in[3];
    const float* wk = (const float*)d_in[4];
    const float* bk = (const float*)d_in[5];
    const float* wv = (const float*)d_in[6];
    const float* bv = (const float*)d_in[7];
    const float* wo = (const float*)d_in[8];
    const float* bo = (const float*)d_in[9];
    const float* w1 = (const float*)d_in[10];
    const float* b1 = (const float*)d_in[11];
    const float* w2 = (const float*)d_in[12];
    const float* b2 = (const float*)d_in[13];
    const float* g1 = (const float*)d_in[14];
    const float* be1= (const float*)d_in[15];
    const float* g2 = (const float*)d_in[16];
    const float* be2= (const float*)d_in[17];
    float* out = (float*)d_out;

    bf16 *xh,*xl,*wqkvh,*wqkvl,*woh,*wol,*w1h,*w1l,*w2h,*w2l;
    bf16 *qkvh,*qkvl,*ch,*cl,*o1h,*o1l,*h1h,*h1l;
    float *bqkv,*attn,*out1,*ffn;
    cudaGetSymbolAddress((void**)&xh,   g_xh);    cudaGetSymbolAddress((void**)&xl,   g_xl);
    cudaGetSymbolAddress((void**)&wqkvh,g_wqkvh); cudaGetSymbolAddress((void**)&wqkvl,g_wqkvl);
    cudaGetSymbolAddress((void**)&woh,  g_woh);   cudaGetSymbolAddress((void**)&wol,  g_wol);
    cudaGetSymbolAddress((void**)&w1h,  g_w1h);   cudaGetSymbolAddress((void**)&w1l,  g_w1l);
    cudaGetSymbolAddress((void**)&w2h,  g_w2h);   cudaGetSymbolAddress((void**)&w2l,  g_w2l);
    cudaGetSymbolAddress((void**)&bqkv, g_bqkv);
    cudaGetSymbolAddress((void**)&qkvh, g_qkvh);  cudaGetSymbolAddress((void**)&qkvl, g_qkvl);
    cudaGetSymbolAddress((void**)&ch,   g_ch);    cudaGetSymbolAddress((void**)&cl,   g_cl);
    cudaGetSymbolAddress((void**)&o1h,  g_o1h);   cudaGetSymbolAddress((void**)&o1l,  g_o1l);
    cudaGetSymbolAddress((void**)&h1h,  g_h1h);   cudaGetSymbolAddress((void**)&h1l,  g_h1l);
    cudaGetSymbolAddress((void**)&attn, g_attn);
    cudaGetSymbolAddress((void**)&out1, g_out1);  cudaGetSymbolAddress((void**)&ffn,  g_ffn);

    cudaFuncSetAttribute(mma_gemm<0>, cudaFuncAttributeMaxDynamicSharedMemorySize, GSMEM);
    cudaFuncSetAttribute(mma_gemm<2>, cudaFuncAttributeMaxDynamicSharedMemorySize, GSMEM);
    cudaFuncSetAttribute(mma_gemm<3>, cudaFuncAttributeMaxDynamicSharedMemorySize, GSMEM);
    cudaFuncSetAttribute(attn_mma,    cudaFuncAttributeMaxDynamicSharedMemorySize, ATT_SMEM);

    // ---- prep ----
    split_kernel<<<MROWS * DMODEL / 1024, 256>>>(x, xh, xl, MROWS * DMODEL);
    dim3 tb(32, 8);
    wtrans_kernel<<<dim3(DMODEL/32, DMODEL/32), tb>>>(wq, wqkvh,              wqkvl,              DMODEL, DMODEL);
    wtrans_kernel<<<dim3(DMODEL/32, DMODEL/32), tb>>>(wk, wqkvh + DMODEL*DMODEL,   wqkvl + DMODEL*DMODEL,   DMODEL, DMODEL);
    wtrans_kernel<<<dim3(DMODEL/32, DMODEL/32), tb>>>(wv, wqkvh + 2*DMODEL*DMODEL, wqkvl + 2*DMODEL*DMODEL, DMODEL, DMODEL);
    wtrans_kernel<<<dim3(DMODEL/32, DMODEL/32), tb>>>(wo, woh, wol, DMODEL, DMODEL);
    wtrans_kernel<<<dim3(DFF/32,    DMODEL/32), tb>>>(w1, w1h, w1l, DMODEL, DFF);
    wtrans_kernel<<<dim3(DMODEL/32, DFF/32),    tb>>>(w2, w2h, w2l, DFF, DMODEL);
    concat_bias<<<(3*DMODEL + 255)/256, 256>>>(bq, bk, bv, bqkv);

    // ---- fused QKV (N=2304), epilogue -> bf16 hi/lo head layout ----
    mma_gemm<3><<<dim3(3*DMODEL/128, MROWS/128), 256, GSMEM>>>(
        xh, xl, wqkvh, wqkvl, bqkv, nullptr, qkvh, qkvl, 3*DMODEL, DMODEL);

    // ---- flash attention (tensor cores) ----
    attn_mma<<<dim3(SEQ/64, BATCH*NHEADS), 128, ATT_SMEM>>>(qkvh, qkvl, ch, cl);

    // ---- O proj + LN1 ----
    dim3 gO(DMODEL/128, MROWS/128);
    mma_gemm<0><<<gO, 256, GSMEM>>>(ch, cl, woh, wol, bo, attn, nullptr, nullptr, DMODEL, DMODEL);
    add_ln_kernel<true><<<MROWS, 256>>>(x, attn, g1, be1, out1, o1h, o1l);

    // ---- FFN ----
    mma_gemm<2><<<dim3(DFF/128, MROWS/128), 256, GSMEM>>>(o1h, o1l, w1h, w1l, b1,
                                                          nullptr, h1h, h1l, DFF, DMODEL);
    mma_gemm<0><<<gO, 256, GSMEM>>>(h1h, h1l, w2h, w2l, b2, ffn, nullptr, nullptr, DMODEL, DFF);
    add_ln_kernel<false><<<MROWS, 256>>>(out1, ffn, g2, be2, out, nullptr, nullptr);
}

// round 7
// speedup vs baseline: 3.3093x; 1.0620x over previous
#include <cuda_runtime.h>
#include <cuda_bf16.h>
#include <math.h>
#include <stdint.h>

// ---------------------------------------------------------------------------
// DecoderLayer on GB300 (compute_100 PTX -> mma.sync HMMA everywhere).
// bf16 3-split GEMMs + bf16 3-split flash attention. fp32 LN.
// B=8, S=1024, D=768, H=12, Dh=64, DFF=3072.
// ---------------------------------------------------------------------------
#define BATCH   8
#define SEQ     1024
#define DMODEL  768
#define NHEADS  12
#define DHEAD   64
#define DFF     3072
#define MROWS   (BATCH*SEQ)          // 8192

typedef __nv_bfloat16 bf16;

// ------------------------- scratch (device globals) -------------------------
__device__ bf16  g_xh  [MROWS*DMODEL],   g_xl  [MROWS*DMODEL];
__device__ bf16  g_wqkvh[3*DMODEL*DMODEL], g_wqkvl[3*DMODEL*DMODEL]; // [2304,768]
__device__ bf16  g_woh [DMODEL*DMODEL],  g_wol [DMODEL*DMODEL];
__device__ bf16  g_w1h [DFF*DMODEL],     g_w1l [DFF*DMODEL];
__device__ bf16  g_w2h [DMODEL*DFF],     g_w2l [DMODEL*DFF];
__device__ float g_bqkv[3*DMODEL];
__device__ bf16  g_qkvh[3*MROWS*DMODEL], g_qkvl[3*MROWS*DMODEL];  // [which][b,h,s,d]
__device__ bf16  g_ch  [MROWS*DMODEL],   g_cl  [MROWS*DMODEL];    // ctx hi/lo
__device__ float g_attn[MROWS*DMODEL];
__device__ float g_out1[MROWS*DMODEL];
__device__ bf16  g_o1h [MROWS*DMODEL],   g_o1l [MROWS*DMODEL];
__device__ bf16  g_h1h [MROWS*DFF],      g_h1l [MROWS*DFF];
__device__ float g_ffn [MROWS*DMODEL];

// ------------------------------ PTX helpers ---------------------------------
__device__ __forceinline__ uint32_t smem_u32(const void* p) {
    uint32_t a;
    asm("{ .reg .u64 t; cvta.to.shared.u64 t, %1; cvt.u32.u64 %0, t; }"
        : "=r"(a) : "l"(p));
    return a;
}

#define CP16(dst, src) \
    asm volatile("cp.async.cg.shared.global [%0], [%1], 16;" \
                 :: "r"(dst), "l"(src))
#define CP_COMMIT() asm volatile("cp.async.commit_group;" ::: "memory")
#define CP_WAIT(n)  asm volatile("cp.async.wait_group %0;" :: "n"(n) : "memory")

#define LDM_X4(r, a) \
    asm volatile("ldmatrix.sync.aligned.m8n8.x4.shared.b16 {%0,%1,%2,%3}, [%4];" \
        : "=r"((r)[0]), "=r"((r)[1]), "=r"((r)[2]), "=r"((r)[3]) : "r"(a))

#define LDM_X4T(r, a) \
    asm volatile("ldmatrix.sync.aligned.m8n8.x4.trans.shared.b16 {%0,%1,%2,%3}, [%4];" \
        : "=r"((r)[0]), "=r"((r)[1]), "=r"((r)[2]), "=r"((r)[3]) : "r"(a))

#define MMA16816(d, a, b0, b1) \
    asm volatile("mma.sync.aligned.m16n8k16.row.col.f32.bf16.bf16.f32 " \
        "{%0,%1,%2,%3}, {%4,%5,%6,%7}, {%8,%9}, {%0,%1,%2,%3};" \
        : "+f"((d)[0]), "+f"((d)[1]), "+f"((d)[2]), "+f"((d)[3]) \
        : "r"((a)[0]), "r"((a)[1]), "r"((a)[2]), "r"((a)[3]), "r"(b0), "r"(b1))

__device__ __forceinline__ void split2(float x, float y, uint32_t& hp, uint32_t& lp) {
    __nv_bfloat162 h = __float22bfloat162_rn(make_float2(x, y));
    float2 r = make_float2(x - __bfloat162float(h.x), y - __bfloat162float(h.y));
    __nv_bfloat162 l = __float22bfloat162_rn(r);
    hp = *(uint32_t*)&h;
    lp = *(uint32_t*)&l;
}

// ---------------------- HMMA GEMM: C = A @ B^T + bias -----------------------
// BM=BN=128, BK=64. 512 threads = 16 warps (4 x 4), warp tile 32x32.
// Double-buffered cp.async, wait-at-top: 1 sync per BK step, load(kt+1)
// overlaps compute(kt). Smem 147456 B -> 1 CTA/SM, 4 warps/SMSP.
// EPI: 0 = fp32 [M,N]; 2 = ReLU + bf16 hi/lo [M,N]; 3 = QKV bf16 hi/lo scatter.
#define GLDA   72                    // padded row stride, elements (144 B)
#define GARR   (128 * GLDA * 2)      // 18432 B per array (Ah/Al/Bh/Bl)
#define GSTG   (4 * GARR)            // 73728 B per stage
#define GSMEM  (2 * GSTG)            // 147456 B

template<int EPI>
__global__ void __launch_bounds__(512, 1)
mma_gemm(const bf16* __restrict__ Ah_, const bf16* __restrict__ Al_,
         const bf16* __restrict__ Bh_, const bf16* __restrict__ Bl_,
         const float* __restrict__ bias,
         float* __restrict__ Cf, bf16* __restrict__ Ch, bf16* __restrict__ Cl,
         int N, int K)
{
    extern __shared__ __align__(128) char smem[];
    const uint32_t sb = smem_u32(smem);
    const int tid  = threadIdx.x;
    const int lane = tid & 31;
    const int wid  = tid >> 5;
    const int wm   = wid & 3;             // 0..3 (M)
    const int wn   = wid >> 2;            // 0..3 (N)
    const int row0 = blockIdx.y * 128, col0 = blockIdx.x * 128;
    const int NT   = K >> 6;              // BK = 64

    float acc[2][4][4];
#pragma unroll
    for (int i = 0; i < 2; i++)
#pragma unroll
        for (int j = 0; j < 4; j++)
#pragma unroll
            for (int r = 0; r < 4; r++) acc[i][j][r] = 0.f;

    // stage loader: 4 arrays x 128 rows x 8 segs(16B) = 4096 chunks / 512 thr
    auto load_stage = [&](int kt, int stg) {
        const int k0 = kt << 6;
        const uint32_t sd = sb + stg * GSTG;
#pragma unroll
        for (int c = tid; c < 4096; c += 512) {
            const int arr = c >> 10, rem = c & 1023;
            const int r = rem >> 3, seg = rem & 7;
            const uint32_t d = sd + arr * GARR + r * 144 + seg * 16;
            if (arr == 0)      CP16(d, Ah_ + (size_t)(row0 + r) * K + k0 + seg * 8);
            else if (arr == 1) CP16(d, Al_ + (size_t)(row0 + r) * K + k0 + seg * 8);
            else if (arr == 2) CP16(d, Bh_ + (size_t)(col0 + r) * K + k0 + seg * 8);
            else               CP16(d, Bl_ + (size_t)(col0 + r) * K + k0 + seg * 8);
        }
    };

    load_stage(0, 0); CP_COMMIT();

    // per-thread ldmatrix byte offsets within an array
    const uint32_t aoff = (uint32_t)(((wm * 32 + (lane & 15)) * GLDA
                                      + ((lane >> 4) << 3)) * 2);
    const uint32_t boff = (uint32_t)(((wn * 32 + ((lane >> 4) << 3) + (lane & 7)) * GLDA
                                      + (((lane >> 3) & 1) << 3)) * 2);

    for (int kt = 0; kt < NT; kt++) {
        CP_WAIT(0);            // stage kt resident (load overlapped compute kt-1)
        __syncthreads();       // + all warps done with buffer (kt+1)&1
        if (kt + 1 < NT) {     // prefetch next stage into the freed buffer
            load_stage(kt + 1, (kt + 1) & 1);
            CP_COMMIT();
        }

        const uint32_t sA = sb + (kt & 1) * GSTG;
#pragma unroll
        for (int ks = 0; ks < 4; ks++) {
            const uint32_t kb = (uint32_t)(ks * 32);   // 16 elems * 2B
            uint32_t ah[2][4], al[2][4], bh[2][4], bl[2][4];
#pragma unroll
            for (int mt = 0; mt < 2; mt++) {
                const uint32_t a = sA + aoff + (uint32_t)(mt * 16 * GLDA * 2) + kb;
                LDM_X4(ah[mt], a);
                LDM_X4(al[mt], a + GARR);
            }
#pragma unroll
            for (int p = 0; p < 2; p++) {
                const uint32_t b = sA + 2 * GARR + boff
                                 + (uint32_t)(p * 16 * GLDA * 2) + kb;
                LDM_X4(bh[p], b);
                LDM_X4(bl[p], b + GARR);
            }
#pragma unroll
            for (int mt = 0; mt < 2; mt++)
#pragma unroll
                for (int nt = 0; nt < 4; nt++) {
                    const int p = nt >> 1, o = (nt & 1) * 2;
                    MMA16816(acc[mt][nt], ah[mt], bh[p][o], bh[p][o + 1]);
                    MMA16816(acc[mt][nt], ah[mt], bl[p][o], bl[p][o + 1]);
                    MMA16816(acc[mt][nt], al[mt], bh[p][o], bh[p][o + 1]);
                }
        }
    }

    // ---- epilogue straight from registers ----
#pragma unroll
    for (int mt = 0; mt < 2; mt++) {
#pragma unroll
        for (int nt = 0; nt < 4; nt++) {
            const int row = row0 + wm * 32 + mt * 16 + (lane >> 2);
            const int col = col0 + wn * 32 + nt * 8 + (lane & 3) * 2;
            const float b0 = __ldg(bias + col), b1 = __ldg(bias + col + 1);
#pragma unroll
            for (int half = 0; half < 2; half++) {
                const int rr = row + half * 8;
                float v0 = acc[mt][nt][half * 2]     + b0;
                float v1 = acc[mt][nt][half * 2 + 1] + b1;
                if (EPI == 0) {
                    *(float2*)&Cf[(size_t)rr * N + col] = make_float2(v0, v1);
                } else if (EPI == 2) {
                    v0 = fmaxf(v0, 0.f); v1 = fmaxf(v1, 0.f);
                    uint32_t hp, lp;
                    split2(v0, v1, hp, lp);
                    *(uint32_t*)&Ch[(size_t)rr * N + col] = hp;
                    *(uint32_t*)&Cl[(size_t)rr * N + col] = lp;
                } else {  // EPI==3: QKV scatter [which][b,h,s,d], Q pre-scaled
                    const int which = col / DMODEL;
                    const int cc = col - which * DMODEL;
                    const int h = cc >> 6, d = cc & 63;
                    if (which == 0) { v0 *= 0.125f; v1 *= 0.125f; }
                    const int b_ = rr >> 10, s = rr & 1023;
                    const size_t dst = (size_t)which * MROWS * DMODEL
                        + (((size_t)(b_ * NHEADS + h)) * SEQ + s) * DHEAD + d;
                    uint32_t hp, lp;
                    split2(v0, v1, hp, lp);
                    *(uint32_t*)&Ch[dst] = hp;
                    *(uint32_t*)&Cl[dst] = lp;
                }
            }
        }
    }
}

// ---------------------- flash attention (HMMA bf16 3-split) ------------------
// BQ=BK=64, 128 threads = 4 warps, each warp 16 q-rows.
#define ASTR   72
#define ATILE  (64 * ASTR * 2)        // 9216 B
#define AKVST  (4 * ATILE)            // 36864 B
#define ATT_SMEM (2 * ATILE + 2 * AKVST)   // 92160 B

__global__ void __launch_bounds__(128, 1)
attn_mma(const bf16* __restrict__ QKVh, const bf16* __restrict__ QKVl,
         bf16* __restrict__ ch, bf16* __restrict__ cl)
{
    extern __shared__ __align__(128) char smem[];
    const uint32_t sb = smem_u32(smem);
    const int tid = threadIdx.x, lane = tid & 31, wid = tid >> 5;
    const int qt = blockIdx.x, bh = blockIdx.y, q0 = qt * 64;
    constexpr size_t MD = (size_t)MROWS * DMODEL;
    const bf16 *Qh = QKVh,        *Kh = QKVh + MD, *Vh = QKVh + 2 * MD;
    const bf16 *Ql = QKVl,        *Kl = QKVl + MD, *Vl = QKVl + 2 * MD;
    const size_t hb = (size_t)bh * SEQ * DHEAD;

    auto load_kv = [&](int kt, int stg) {
        const size_t gb = hb + (size_t)(kt * 64) * 64;
        const uint32_t sd = sb + 2 * ATILE + stg * AKVST;
        for (int i = tid; i < 512; i += 128) {
            const int row = i >> 3, seg = i & 7;
            const uint32_t d0 = sd + row * 144 + seg * 16;
            const size_t g = gb + row * 64 + seg * 8;
            CP16(d0,             Kh + g);
            CP16(d0 + ATILE,     Kl + g);
            CP16(d0 + 2 * ATILE, Vh + g);
            CP16(d0 + 3 * ATILE, Vl + g);
        }
    };

    {
        const size_t gq = hb + (size_t)q0 * 64;
        for (int i = tid; i < 512; i += 128) {
            const int row = i >> 3, seg = i & 7;
            const uint32_t d0 = sb + row * 144 + seg * 16;
            const size_t g = gq + row * 64 + seg * 8;
            CP16(d0,         Qh + g);
            CP16(d0 + ATILE, Ql + g);
        }
        load_kv(0, 0);
    }
    CP_COMMIT();
    load_kv(qt >= 1 ? 1 : 0, 1);
    CP_COMMIT();

    uint32_t qh[4][4], ql[4][4];
    float oacc[8][4];
#pragma unroll
    for (int nt = 0; nt < 8; nt++)
#pragma unroll
        for (int e = 0; e < 4; e++) oacc[nt][e] = 0.f;
    float m0 = -1e30f, m1 = -1e30f, l0 = 0.f, l1 = 0.f;

    const int lcol  = (lane & 3) * 2;
    const int rowg0 = q0 + wid * 16 + (lane >> 2);

    for (int kt = 0; kt <= qt; kt++) {
        CP_WAIT(1);
        __syncthreads();
        if (kt == 0) {
#pragma unroll
            for (int kc = 0; kc < 4; kc++) {
                const uint32_t a = sb + (uint32_t)(((wid * 16 + (lane & 15)) * ASTR
                                    + ((lane >> 4) << 3) + kc * 16) * 2);
                LDM_X4(qh[kc], a);
                LDM_X4(ql[kc], a + ATILE);
            }
        }
        const uint32_t kvb = sb + 2 * ATILE + (kt & 1) * AKVST;

        float sacc[8][4];
#pragma unroll
        for (int nt = 0; nt < 8; nt++)
#pragma unroll
            for (int e = 0; e < 4; e++) sacc[nt][e] = 0.f;

#pragma unroll
        for (int kc = 0; kc < 4; kc++) {
            uint32_t kh2[8][2], kl2[8][2];
#pragma unroll
            for (int g = 0; g < 4; g++) {
                const uint32_t a = kvb + (uint32_t)(((g * 16 + ((lane >> 4) << 3)
                    + (lane & 7)) * ASTR + (((lane >> 3) & 1) << 3) + kc * 16) * 2);
                uint32_t r[4];
                LDM_X4(r, a);
                kh2[2*g][0]=r[0]; kh2[2*g][1]=r[1]; kh2[2*g+1][0]=r[2]; kh2[2*g+1][1]=r[3];
                LDM_X4(r, a + ATILE);
                kl2[2*g][0]=r[0]; kl2[2*g][1]=r[1]; kl2[2*g+1][0]=r[2]; kl2[2*g+1][1]=r[3];
            }
#pragma unroll
            for (int nt = 0; nt < 8; nt++) {
                MMA16816(sacc[nt], qh[kc], kh2[nt][0], kh2[nt][1]);
                MMA16816(sacc[nt], qh[kc], kl2[nt][0], kl2[nt][1]);
                MMA16816(sacc[nt], ql[kc], kh2[nt][0], kh2[nt][1]);
            }
        }

        if (kt == qt) {
#pragma unroll
            for (int nt = 0; nt < 8; nt++) {
                const int colb = kt * 64 + nt * 8 + lcol;
                if (colb     > rowg0)     sacc[nt][0] = -1e30f;
                if (colb + 1 > rowg0)     sacc[nt][1] = -1e30f;
                if (colb     > rowg0 + 8) sacc[nt][2] = -1e30f;
                if (colb + 1 > rowg0 + 8) sacc[nt][3] = -1e30f;
            }
        }

        float tm0 = -1e30f, tm1 = -1e30f;
#pragma unroll
        for (int nt = 0; nt < 8; nt++) {
            tm0 = fmaxf(tm0, fmaxf(sacc[nt][0], sacc[nt][1]));
            tm1 = fmaxf(tm1, fmaxf(sacc[nt][2], sacc[nt][3]));
        }
        tm0 = fmaxf(tm0, __shfl_xor_sync(0xffffffffu, tm0, 1));
        tm0 = fmaxf(tm0, __shfl_xor_sync(0xffffffffu, tm0, 2));
        tm1 = fmaxf(tm1, __shfl_xor_sync(0xffffffffu, tm1, 1));
        tm1 = fmaxf(tm1, __shfl_xor_sync(0xffffffffu, tm1, 2));

        const float mn0 = fmaxf(m0, tm0), mn1 = fmaxf(m1, tm1);
        const float a0 = __expf(m0 - mn0), a1 = __expf(m1 - mn1);
        m0 = mn0; m1 = mn1;

        float s0 = 0.f, s1 = 0.f;
#pragma unroll
        for (int nt = 0; nt < 8; nt++) {
            sacc[nt][0] = __expf(sacc[nt][0] - mn0); s0 += sacc[nt][0];
            sacc[nt][1] = __expf(sacc[nt][1] - mn0); s0 += sacc[nt][1];
            sacc[nt][2] = __expf(sacc[nt][2] - mn1); s1 += sacc[nt][2];
            sacc[nt][3] = __expf(sacc[nt][3] - mn1); s1 += sacc[nt][3];
        }
        s0 += __shfl_xor_sync(0xffffffffu, s0, 1);
        s0 += __shfl_xor_sync(0xffffffffu, s0, 2);
        s1 += __shfl_xor_sync(0xffffffffu, s1, 1);
        s1 += __shfl_xor_sync(0xffffffffu, s1, 2);
        l0 = l0 * a0 + s0;
        l1 = l1 * a1 + s1;
#pragma unroll
        for (int nt = 0; nt < 8; nt++) {
            oacc[nt][0] *= a0; oacc[nt][1] *= a0;
            oacc[nt][2] *= a1; oacc[nt][3] *= a1;
        }

        const uint32_t vb = kvb + 2 * ATILE;
#pragma unroll
        for (int j = 0; j < 4; j++) {
            uint32_t vh2[8][2], vl2[8][2];
#pragma unroll
            for (int ng = 0; ng < 4; ng++) {
                const uint32_t a = vb + (uint32_t)(((j * 16 + (lane & 15)) * ASTR
                                    + ng * 16 + ((lane >> 4) << 3)) * 2);
                uint32_t r[4];
                LDM_X4T(r, a);
                vh2[2*ng][0]=r[0]; vh2[2*ng][1]=r[1]; vh2[2*ng+1][0]=r[2]; vh2[2*ng+1][1]=r[3];
                LDM_X4T(r, a + ATILE);
                vl2[2*ng][0]=r[0]; vl2[2*ng][1]=r[1]; vl2[2*ng+1][0]=r[2]; vl2[2*ng+1][1]=r[3];
            }
            uint32_t ph[4], pl[4];
            split2(sacc[2*j][0],   sacc[2*j][1],   ph[0], pl[0]);
            split2(sacc[2*j][2],   sacc[2*j][3],   ph[1], pl[1]);
            split2(sacc[2*j+1][0], sacc[2*j+1][1], ph[2], pl[2]);
            split2(sacc[2*j+1][2], sacc[2*j+1][3], ph[3], pl[3]);
#pragma unroll
            for (int nt = 0; nt < 8; nt++) {
                MMA16816(oacc[nt], ph, vh2[nt][0], vh2[nt][1]);
                MMA16816(oacc[nt], ph, vl2[nt][0], vl2[nt][1]);
                MMA16816(oacc[nt], pl, vh2[nt][0], vh2[nt][1]);
            }
        }
        __syncthreads();
        if (kt + 2 <= qt) load_kv(kt + 2, kt & 1);
        CP_COMMIT();
    }

    const float i0 = 1.f / l0, i1 = 1.f / l1;
    const int b_ = bh / NHEADS, h = bh % NHEADS;
#pragma unroll
    for (int nt = 0; nt < 8; nt++) {
        const int d = nt * 8 + lcol;
        const size_t r0i = ((size_t)(b_ * SEQ + rowg0)) * DMODEL + h * 64 + d;
        const size_t r1i = r0i + (size_t)8 * DMODEL;
        uint32_t hp, lp;
        split2(oacc[nt][0] * i0, oacc[nt][1] * i0, hp, lp);
        *(uint32_t*)&ch[r0i] = hp;
        *(uint32_t*)&cl[r0i] = lp;
        split2(oacc[nt][2] * i1, oacc[nt][3] * i1, hp, lp);
        *(uint32_t*)&ch[r1i] = hp;
        *(uint32_t*)&cl[r1i] = lp;
    }
}

// ---------------------- prep kernels ----------------------------------------
__global__ void __launch_bounds__(256)
split_kernel(const float* __restrict__ src, bf16* __restrict__ hi,
             bf16* __restrict__ lo, int n)
{
    int i0 = (blockIdx.x * 256 + threadIdx.x) * 4;
    if (i0 >= n) return;
#pragma unroll
    for (int j = 0; j < 4; j++) {
        float v = src[i0 + j];
        bf16 h = __float2bfloat16(v);
        hi[i0 + j] = h;
        lo[i0 + j] = __float2bfloat16(v - __bfloat162float(h));
    }
}

__global__ void __launch_bounds__(256)
wtrans_kernel(const float* __restrict__ src, bf16* __restrict__ dh,
              bf16* __restrict__ dl, int K, int N)
{
    __shared__ float t[32][33];
    const int bx = blockIdx.x * 32;
    const int by = blockIdx.y * 32;
    const int tx = threadIdx.x, ty = threadIdx.y;
#pragma unroll
    for (int i = 0; i < 32; i += 8)
        t[ty + i][tx] = src[(size_t)(by + ty + i) * N + bx + tx];
    __syncthreads();
#pragma unroll
    for (int i = 0; i < 32; i += 8) {
        float v = t[tx][ty + i];
        bf16 h = __float2bfloat16(v);
        size_t o = (size_t)(bx + ty + i) * K + by + tx;
        dh[o] = h;
        dl[o] = __float2bfloat16(v - __bfloat162float(h));
    }
}

__global__ void __launch_bounds__(256)
concat_bias(const float* __restrict__ bq, const float* __restrict__ bk,
            const float* __restrict__ bv, float* __restrict__ out)
{
    int i = blockIdx.x * 256 + threadIdx.x;
    if (i >= 3 * DMODEL) return;
    out[i] = i < DMODEL ? bq[i] : (i < 2 * DMODEL ? bk[i - DMODEL] : bv[i - 2 * DMODEL]);
}

// ----------------------- fused residual add + LayerNorm ---------------------
template<bool HILO>
__global__ void __launch_bounds__(256)
add_ln_kernel(const float* __restrict__ a, const float* __restrict__ b,
              const float* __restrict__ g, const float* __restrict__ be,
              float* __restrict__ out, bf16* __restrict__ ohi, bf16* __restrict__ olo)
{
    __shared__ float red[8];
    const int row = blockIdx.x;
    const int t   = threadIdx.x;
    const float* ar = a + (size_t)row * DMODEL;
    const float* br = b + (size_t)row * DMODEL;

    float v0 = ar[t]       + br[t];
    float v1 = ar[t + 256] + br[t + 256];
    float v2 = ar[t + 512] + br[t + 512];

    float sum = v0 + v1 + v2;
#pragma unroll
    for (int off = 16; off; off >>= 1) sum += __shfl_xor_sync(0xffffffffu, sum, off);
    if ((t & 31) == 0) red[t >> 5] = sum;
    __syncthreads();
    float tot = 0.f;
#pragma unroll
    for (int w = 0; w < 8; w++) tot += red[w];
    const float mu = tot * (1.f / DMODEL);
    __syncthreads();

    float d0 = v0 - mu, d1 = v1 - mu, d2 = v2 - mu;
    float vs = d0 * d0 + d1 * d1 + d2 * d2;
#pragma unroll
    for (int off = 16; off; off >>= 1) vs += __shfl_xor_sync(0xffffffffu, vs, off);
    if ((t & 31) == 0) red[t >> 5] = vs;
    __syncthreads();
    tot = 0.f;
#pragma unroll
    for (int w = 0; w < 8; w++) tot += red[w];
    const float rstd = rsqrtf(tot * (1.f / DMODEL) + 1e-6f);

    float* o = out + (size_t)row * DMODEL;
    float r0 = g[t]       * d0 * rstd + be[t];
    float r1 = g[t + 256] * d1 * rstd + be[t + 256];
    float r2 = g[t + 512] * d2 * rstd + be[t + 512];
    o[t] = r0; o[t + 256] = r1; o[t + 512] = r2;
    if (HILO) {
        size_t base = (size_t)row * DMODEL;
#pragma unroll
        for (int j = 0; j < 3; j++) {
            float v = j == 0 ? r0 : (j == 1 ? r1 : r2);
            int idx = t + j * 256;
            bf16 h = __float2bfloat16(v);
            ohi[base + idx] = h;
            olo[base + idx] = __float2bfloat16(v - __bfloat162float(h));
        }
    }
}

// --------------------------------- launch ------------------------------------
extern "C" void kernel_launch(void* const* d_in, const int* in_sizes, int n_in,
                              void* d_out, int out_size)
{
    const float* x  = (const float*)d_in[0];
    const float* wq = (const float*)d_in[2];
    const float* bq = (const float*)d_in[3];
    const float* wk = (const float*)d_in[4];
    const float* bk = (const float*)d_in[5];
    const float* wv = (const float*)d_in[6];
    const float* bv = (const float*)d_in[7];
    const float* wo = (const float*)d_in[8];
    const float* bo = (const float*)d_in[9];
    const float* w1 = (const float*)d_in[10];
    const float* b1 = (const float*)d_in[11];
    const float* w2 = (const float*)d_in[12];
    const float* b2 = (const float*)d_in[13];
    const float* g1 = (const float*)d_in[14];
    const float* be1= (const float*)d_in[15];
    const float* g2 = (const float*)d_in[16];
    const float* be2= (const float*)d_in[17];
    float* out = (float*)d_out;

    bf16 *xh,*xl,*wqkvh,*wqkvl,*woh,*wol,*w1h,*w1l,*w2h,*w2l;
    bf16 *qkvh,*qkvl,*ch,*cl,*o1h,*o1l,*h1h,*h1l;
    float *bqkv,*attn,*out1,*ffn;
    cudaGetSymbolAddress((void**)&xh,   g_xh);    cudaGetSymbolAddress((void**)&xl,   g_xl);
    cudaGetSymbolAddress((void**)&wqkvh,g_wqkvh); cudaGetSymbolAddress((void**)&wqkvl,g_wqkvl);
    cudaGetSymbolAddress((void**)&woh,  g_woh);   cudaGetSymbolAddress((void**)&wol,  g_wol);
    cudaGetSymbolAddress((void**)&w1h,  g_w1h);   cudaGetSymbolAddress((void**)&w1l,  g_w1l);
    cudaGetSymbolAddress((void**)&w2h,  g_w2h);   cudaGetSymbolAddress((void**)&w2l,  g_w2l);
    cudaGetSymbolAddress((void**)&bqkv, g_bqkv);
    cudaGetSymbolAddress((void**)&qkvh, g_qkvh);  cudaGetSymbolAddress((void**)&qkvl, g_qkvl);
    cudaGetSymbolAddress((void**)&ch,   g_ch);    cudaGetSymbolAddress((void**)&cl,   g_cl);
    cudaGetSymbolAddress((void**)&o1h,  g_o1h);   cudaGetSymbolAddress((void**)&o1l,  g_o1l);
    cudaGetSymbolAddress((void**)&h1h,  g_h1h);   cudaGetSymbolAddress((void**)&h1l,  g_h1l);
    cudaGetSymbolAddress((void**)&attn, g_attn);
    cudaGetSymbolAddress((void**)&out1, g_out1);  cudaGetSymbolAddress((void**)&ffn,  g_ffn);

    cudaFuncSetAttribute(mma_gemm<0>, cudaFuncAttributeMaxDynamicSharedMemorySize, GSMEM);
    cudaFuncSetAttribute(mma_gemm<2>, cudaFuncAttributeMaxDynamicSharedMemorySize, GSMEM);
    cudaFuncSetAttribute(mma_gemm<3>, cudaFuncAttributeMaxDynamicSharedMemorySize, GSMEM);
    cudaFuncSetAttribute(attn_mma,    cudaFuncAttributeMaxDynamicSharedMemorySize, ATT_SMEM);

    // ---- prep ----
    split_kernel<<<MROWS * DMODEL / 1024, 256>>>(x, xh, xl, MROWS * DMODEL);
    dim3 tb(32, 8);
    wtrans_kernel<<<dim3(DMODEL/32, DMODEL/32), tb>>>(wq, wqkvh,              wqkvl,              DMODEL, DMODEL);
    wtrans_kernel<<<dim3(DMODEL/32, DMODEL/32), tb>>>(wk, wqkvh + DMODEL*DMODEL,   wqkvl + DMODEL*DMODEL,   DMODEL, DMODEL);
    wtrans_kernel<<<dim3(DMODEL/32, DMODEL/32), tb>>>(wv, wqkvh + 2*DMODEL*DMODEL, wqkvl + 2*DMODEL*DMODEL, DMODEL, DMODEL);
    wtrans_kernel<<<dim3(DMODEL/32, DMODEL/32), tb>>>(wo, woh, wol, DMODEL, DMODEL);
    wtrans_kernel<<<dim3(DFF/32,    DMODEL/32), tb>>>(w1, w1h, w1l, DMODEL, DFF);
    wtrans_kernel<<<dim3(DMODEL/32, DFF/32),    tb>>>(w2, w2h, w2l, DFF, DMODEL);
    concat_bias<<<(3*DMODEL + 255)/256, 256>>>(bq, bk, bv, bqkv);

    // ---- fused QKV (N=2304), epilogue -> bf16 hi/lo head layout ----
    mma_gemm<3><<<dim3(3*DMODEL/128, MROWS/128), 512, GSMEM>>>(
        xh, xl, wqkvh, wqkvl, bqkv, nullptr, qkvh, qkvl, 3*DMODEL, DMODEL);

    // ---- flash attention (tensor cores) ----
    attn_mma<<<dim3(SEQ/64, BATCH*NHEADS), 128, ATT_SMEM>>>(qkvh, qkvl, ch, cl);

    // ---- O proj + LN1 ----
    dim3 gO(DMODEL/128, MROWS/128);
    mma_gemm<0><<<gO, 512, GSMEM>>>(ch, cl, woh, wol, bo, attn, nullptr, nullptr, DMODEL, DMODEL);
    add_ln_kernel<true><<<MROWS, 256>>>(x, attn, g1, be1, out1, o1h, o1l);

    // ---- FFN ----
    mma_gemm<2><<<dim3(DFF/128, MROWS/128), 512, GSMEM>>>(o1h, o1l, w1h, w1l, b1,
                                                          nullptr, h1h, h1l, DFF, DMODEL);
    mma_gemm<0><<<gO, 512, GSMEM>>>(h1h, h1l, w2h, w2l, b2, ffn, nullptr, nullptr, DMODEL, DFF);
    add_ln_kernel<false><<<MROWS, 256>>>(out1, ffn, g2, be2, out, nullptr, nullptr);
}